// round 13
// baseline (speedup 1.0000x reference)
#include <cuda_runtime.h>
#include <cuda_fp16.h>
#include <math.h>

#define N_NODES 20000
#define N_EDGES 400000
#define DIM 128
#define NB 16
#define ZD 16
#define NLAYERS 2
#define KT1 (NB*DIM)   // 2048
#define KT0 (NB*ZD)    // 256
#define MAXDEG 96      // padded CSR stride (true max degree ~45)

// ---------------- device scratch (static, no allocations) ----------------
__device__ __half g_A[(size_t)N_NODES*KT1];     // aggregated T rows (fp16)
__device__ __half g_z16h[N_NODES*32];           // layer0 features, padded K2=32
__device__ __half g_zih[N_NODES*DIM];           // fp16 layer0 output
__device__ __half g_Vh0[KT0*DIM];               // V0.reshape(-1,128) fp16
__device__ __half g_Vh1[KT1*DIM];               // V1.reshape(-1,128) fp16
__device__ __half g_Ws0h[32*DIM];               // Ws0 padded to 32 rows, fp16
__device__ __half g_Ws1h[DIM*DIM];              // Ws1 fp16
__device__ __half g_Wah[NLAYERS*3*DIM*DIM];     // onsite Wa fp16
__device__ __half g_Wbh[NLAYERS*3*DIM*DIM];     // onsite Wb fp16

// padded CSR by src. g_curS starts zero (module load); k_edgeT1 re-zeroes.
__device__ int   g_curS[N_NODES];
__device__ int   g_dstS[(size_t)N_NODES*MAXDEG];
__device__ float g_distS[(size_t)N_NODES*MAXDEG];
__device__ float g_swS[(size_t)N_NODES*MAXDEG];

__device__ __forceinline__ float silu_f(float x) {
    return x / (1.0f + __expf(-x));
}

// ---------------- merged preprocessing + padded-CSR fill ------------------
__global__ void k_prep(const int* __restrict__ species, const float* __restrict__ Z,
                       const float* __restrict__ V0, const float* __restrict__ V1,
                       const float* __restrict__ Ws0, const float* __restrict__ Ws1,
                       const float* __restrict__ Wa, const float* __restrict__ Wb,
                       const int* __restrict__ esrc, const int* __restrict__ edst,
                       const float* __restrict__ dist, const float* __restrict__ sw)
{
    int t = blockIdx.x * blockDim.x + threadIdx.x;
    if (t < N_NODES * 32) {
        int n = t >> 5, c = t & 31;
        g_z16h[t] = __float2half(c < ZD ? Z[species[n] * ZD + c] : 0.0f);
    }
    if (t < KT1 * DIM) g_Vh1[t] = __float2half(V1[t]);
    if (t < KT0 * DIM) g_Vh0[t] = __float2half(V0[t]);
    if (t < NLAYERS * 3 * DIM * DIM) {
        g_Wah[t] = __float2half(Wa[t]);
        g_Wbh[t] = __float2half(Wb[t]);
    }
    if (t < 32 * DIM) {
        int r = t >> 7;
        g_Ws0h[t] = __float2half(r < ZD ? Ws0[t] : 0.0f);
    }
    if (t < DIM * DIM) g_Ws1h[t] = __float2half(Ws1[t]);
    if (t < N_EDGES) {
        int s = esrc[t];
        int r = atomicAdd(&g_curS[s], 1);    // curS zero on entry
        if (r < MAXDEG) {
            size_t pos = (size_t)s * MAXDEG + r;
            g_dstS[pos]  = edst[t];
            g_distS[pos] = dist[t];
            g_swS[pos]   = sw[t];
        }
    }
}

// ---------------- edge aggregation via tensor cores -----------------------
__global__ __launch_bounds__(256) void k_edgeT1() {
    __shared__ __half SA[8][16][24];
    __shared__ __half SB[8][16][136];

    const int warp = threadIdx.x >> 5;
    const int lane = threadIdx.x & 31;
    const int n = blockIdx.x * 8 + warp;
    if (n >= N_NODES) return;
    int deg = g_curS[n];
    if (deg > MAXDEG) deg = MAXDEG;
    __syncwarp();
    if (lane == 0) g_curS[n] = 0;           // self-clean for next replay
    const size_t p0 = (size_t)n * MAXDEG;

    float acc[16][4];
    #pragma unroll
    for (int nt = 0; nt < 16; nt++)
        #pragma unroll
        for (int i = 0; i < 4; i++) acc[nt][i] = 0.0f;

    const int el = lane & 15, hi = lane >> 4;
    const float sigma  = 0.8f / 15.0f;
    const float rsigma = 15.0f / 0.8f;

    for (int c = 0; c < deg; c += 16) {
        const bool v = (c + el < deg);
        const size_t p = p0 + c + el;
        const int dst   = v ? g_dstS[p]  : 0;
        const float di  = v ? g_distS[p] : 1.0f;
        const float sw  = v ? g_swS[p]   : 0.0f;
        const float rinv = 1.0f / di;

        #pragma unroll
        for (int j = 0; j < 8; j++) {
            const float mu = 0.2f + (float)(hi * 8 + j) * sigma;
            const float x = (rinv - mu) * rsigma;
            SA[warp][hi * 8 + j][el] = __float2half(__expf(-0.5f * x * x) * sw);
        }
        #pragma unroll
        for (int r2 = 0; r2 < 8; r2++) {
            const int row = r2 * 2 + hi;
            const int rdst = __shfl_sync(0xffffffffu, dst, row);
            *(uint4*)&SB[warp][row][el * 8] =
                *(const uint4*)&g_zih[(size_t)rdst * DIM + el * 8];
        }
        __syncwarp();

        unsigned af[4];
        {
            const __half* pA = &SA[warp][el][hi * 8];
            unsigned addr = (unsigned)__cvta_generic_to_shared(pA);
            asm volatile("ldmatrix.sync.aligned.m8n8.x4.shared.b16 {%0,%1,%2,%3}, [%4];"
                : "=r"(af[0]), "=r"(af[1]), "=r"(af[2]), "=r"(af[3]) : "r"(addr));
        }
        #pragma unroll
        for (int q = 0; q < 8; q++) {
            unsigned bf[2][2];
            const __half* pB = &SB[warp][el][q * 16 + hi * 8];
            unsigned addr = (unsigned)__cvta_generic_to_shared(pB);
            asm volatile("ldmatrix.sync.aligned.m8n8.x4.trans.shared.b16 {%0,%1,%2,%3}, [%4];"
                : "=r"(bf[0][0]), "=r"(bf[0][1]), "=r"(bf[1][0]), "=r"(bf[1][1])
                : "r"(addr));
            #pragma unroll
            for (int h = 0; h < 2; h++) {
                asm volatile(
                    "mma.sync.aligned.m16n8k16.row.col.f32.f16.f16.f32 "
                    "{%0,%1,%2,%3}, {%4,%5,%6,%7}, {%8,%9}, {%0,%1,%2,%3};"
                    : "+f"(acc[q*2+h][0]), "+f"(acc[q*2+h][1]),
                      "+f"(acc[q*2+h][2]), "+f"(acc[q*2+h][3])
                    : "r"(af[0]), "r"(af[1]), "r"(af[2]), "r"(af[3]),
                      "r"(bf[h][0]), "r"(bf[h][1]));
            }
        }
        __syncwarp();
    }

    const int g4 = lane >> 2, t4 = lane & 3;
    __half* Ap = g_A + (size_t)n * KT1;
    #pragma unroll
    for (int nt = 0; nt < 16; nt++) {
        *(__half2*)&Ap[(size_t)g4 * DIM + nt*8 + 2*t4] =
            __floats2half2_rn(acc[nt][0], acc[nt][1]);
        *(__half2*)&Ap[(size_t)(g4 + 8) * DIM + nt*8 + 2*t4] =
            __floats2half2_rn(acc[nt][2], acc[nt][3]);
    }
}

__global__ __launch_bounds__(256) void k_edgeT0() {
    __shared__ __half SA[8][16][24];
    __shared__ __half SB[8][16][24];

    const int warp = threadIdx.x >> 5;
    const int lane = threadIdx.x & 31;
    const int n = blockIdx.x * 8 + warp;
    if (n >= N_NODES) return;
    int deg = g_curS[n];
    if (deg > MAXDEG) deg = MAXDEG;
    const size_t p0 = (size_t)n * MAXDEG;

    float acc[2][4];
    #pragma unroll
    for (int nt = 0; nt < 2; nt++)
        #pragma unroll
        for (int i = 0; i < 4; i++) acc[nt][i] = 0.0f;

    const int el = lane & 15, hi = lane >> 4;
    const float sigma  = 0.8f / 15.0f;
    const float rsigma = 15.0f / 0.8f;

    for (int c = 0; c < deg; c += 16) {
        const bool v = (c + el < deg);
        const size_t p = p0 + c + el;
        const int dst   = v ? g_dstS[p]  : 0;
        const float di  = v ? g_distS[p] : 1.0f;
        const float sw  = v ? g_swS[p]   : 0.0f;
        const float rinv = 1.0f / di;

        #pragma unroll
        for (int j = 0; j < 8; j++) {
            const float mu = 0.2f + (float)(hi * 8 + j) * sigma;
            const float x = (rinv - mu) * rsigma;
            SA[warp][hi * 8 + j][el] = __float2half(__expf(-0.5f * x * x) * sw);
        }
        {
            const int row = lane >> 1;
            const int rdst = __shfl_sync(0xffffffffu, dst, row);
            *(uint4*)&SB[warp][row][(lane & 1) * 8] =
                *(const uint4*)&g_z16h[rdst * 32 + (lane & 1) * 8];
        }
        __syncwarp();

        unsigned af[4];
        {
            const __half* pA = &SA[warp][el][hi * 8];
            unsigned addr = (unsigned)__cvta_generic_to_shared(pA);
            asm volatile("ldmatrix.sync.aligned.m8n8.x4.shared.b16 {%0,%1,%2,%3}, [%4];"
                : "=r"(af[0]), "=r"(af[1]), "=r"(af[2]), "=r"(af[3]) : "r"(addr));
        }
        unsigned bf[2][2];
        {
            const __half* pB = &SB[warp][el][hi * 8];
            unsigned addr = (unsigned)__cvta_generic_to_shared(pB);
            asm volatile("ldmatrix.sync.aligned.m8n8.x4.trans.shared.b16 {%0,%1,%2,%3}, [%4];"
                : "=r"(bf[0][0]), "=r"(bf[0][1]), "=r"(bf[1][0]), "=r"(bf[1][1])
                : "r"(addr));
        }
        #pragma unroll
        for (int h = 0; h < 2; h++) {
            asm volatile(
                "mma.sync.aligned.m16n8k16.row.col.f32.f16.f16.f32 "
                "{%0,%1,%2,%3}, {%4,%5,%6,%7}, {%8,%9}, {%0,%1,%2,%3};"
                : "+f"(acc[h][0]), "+f"(acc[h][1]), "+f"(acc[h][2]), "+f"(acc[h][3])
                : "r"(af[0]), "r"(af[1]), "r"(af[2]), "r"(af[3]),
                  "r"(bf[h][0]), "r"(bf[h][1]));
        }
        __syncwarp();
    }

    const int g4 = lane >> 2, t4 = lane & 3;
    __half* Ap = g_A + (size_t)n * KT0;
    #pragma unroll
    for (int nt = 0; nt < 2; nt++) {
        *(__half2*)&Ap[g4 * ZD + nt*8 + 2*t4] =
            __floats2half2_rn(acc[nt][0], acc[nt][1]);
        *(__half2*)&Ap[(g4 + 8) * ZD + nt*8 + 2*t4] =
            __floats2half2_rn(acc[nt][2], acc[nt][3]);
    }
}

// ---------------- fused node pipeline -------------------------------------
#define CPA16(dst, src, bytes) \
    asm volatile("cp.async.cg.shared.global [%0], [%1], 16, %2;" \
                 :: "r"(dst), "l"(src), "r"(bytes))

template<int LAYER>
__global__ __launch_bounds__(256) void k_nodeP(
    const __half* __restrict__ A, const __half* __restrict__ B,
    const __half* __restrict__ A2, const __half* __restrict__ W2,
    const float* __restrict__ bs,
    const __half* __restrict__ WaBase, const float* __restrict__ baBase,
    const __half* __restrict__ WbBase, const float* __restrict__ bbBase,
    __half* __restrict__ zih_out, float* __restrict__ out,
    int K, int K2)
{
    extern __shared__ char sm[];
    __half (*As)[136] = (__half(*)[136])sm;                       // 64x136
    __half (*Ws)[136] = (__half(*)[136])(sm + 17408);             // 128x136
    float  (*R)[DIM]  = (float (*)[DIM])(sm + 52224);             // 64x128 fp32
    __half (*Ag)[64][40]  = (__half(*)[64][40]) (sm + 17408);
    __half (*Bg)[32][136] = (__half(*)[32][136])(sm + 17408 + 10240);

    const int t = threadIdx.x;
    const int warp = t >> 5, lane = t & 31;
    const int wm = (warp & 1) * 32, wn = (warp >> 1) * 32;
    const int m0 = blockIdx.x * 64;
    const int g4 = lane >> 2, t4 = lane & 3;

    const int arow = t >> 2, ak = (t & 3) * 8;
    const int brow = t >> 4, bcol = (t & 15) * 8;
    const int gm = m0 + arow;
    const int apred = (gm < N_NODES) ? 16 : 0;
    const __half* Abase = &A[(size_t)gm * K];

    float acc[2][4][4];
    #pragma unroll
    for (int mt = 0; mt < 2; mt++)
        #pragma unroll
        for (int nt = 0; nt < 4; nt++)
            #pragma unroll
            for (int i = 0; i < 4; i++) acc[mt][nt][i] = 0.0f;

    const int T = K >> 5;

    {
        unsigned da = (unsigned)__cvta_generic_to_shared(&Ag[0][arow][ak]);
        CPA16(da, Abase + ak, apred);
        unsigned db0 = (unsigned)__cvta_generic_to_shared(&Bg[0][brow][bcol]);
        unsigned db1 = (unsigned)__cvta_generic_to_shared(&Bg[0][16 + brow][bcol]);
        CPA16(db0, &B[(size_t)brow * DIM + bcol], 16);
        CPA16(db1, &B[(size_t)(16 + brow) * DIM + bcol], 16);
        asm volatile("cp.async.commit_group;");
    }

    for (int tt = 0; tt < T; tt++) {
        if (tt + 1 < T) {
            const int buf = (tt + 1) & 1, k0 = (tt + 1) * 32;
            unsigned da = (unsigned)__cvta_generic_to_shared(&Ag[buf][arow][ak]);
            CPA16(da, Abase + k0 + ak, apred);
            unsigned db0 = (unsigned)__cvta_generic_to_shared(&Bg[buf][brow][bcol]);
            unsigned db1 = (unsigned)__cvta_generic_to_shared(&Bg[buf][16 + brow][bcol]);
            CPA16(db0, &B[(size_t)(k0 + brow) * DIM + bcol], 16);
            CPA16(db1, &B[(size_t)(k0 + 16 + brow) * DIM + bcol], 16);
            asm volatile("cp.async.commit_group;");
            asm volatile("cp.async.wait_group 1;");
        } else {
            asm volatile("cp.async.wait_group 0;");
        }
        __syncthreads();

        const int buf = tt & 1;
        #pragma unroll
        for (int sub = 0; sub < 2; sub++) {
            const int kc = sub * 16;
            unsigned af[2][4];
            #pragma unroll
            for (int mt = 0; mt < 2; mt++) {
                const __half* p = &Ag[buf][wm + mt*16 + (lane & 15)][kc + ((lane >> 4) << 3)];
                unsigned addr = (unsigned)__cvta_generic_to_shared(p);
                asm volatile("ldmatrix.sync.aligned.m8n8.x4.shared.b16 {%0,%1,%2,%3}, [%4];"
                    : "=r"(af[mt][0]), "=r"(af[mt][1]), "=r"(af[mt][2]), "=r"(af[mt][3])
                    : "r"(addr));
            }
            unsigned bf[4][2];
            #pragma unroll
            for (int q = 0; q < 2; q++) {
                const __half* p = &Bg[buf][kc + (lane & 15)][wn + q*16 + ((lane >> 4) << 3)];
                unsigned addr = (unsigned)__cvta_generic_to_shared(p);
                asm volatile("ldmatrix.sync.aligned.m8n8.x4.trans.shared.b16 {%0,%1,%2,%3}, [%4];"
                    : "=r"(bf[q*2][0]), "=r"(bf[q*2][1]), "=r"(bf[q*2+1][0]), "=r"(bf[q*2+1][1])
                    : "r"(addr));
            }
            #pragma unroll
            for (int mt = 0; mt < 2; mt++)
                #pragma unroll
                for (int nt = 0; nt < 4; nt++) {
                    asm volatile(
                        "mma.sync.aligned.m16n8k16.row.col.f32.f16.f16.f32 "
                        "{%0,%1,%2,%3}, {%4,%5,%6,%7}, {%8,%9}, {%0,%1,%2,%3};"
                        : "+f"(acc[mt][nt][0]), "+f"(acc[mt][nt][1]),
                          "+f"(acc[mt][nt][2]), "+f"(acc[mt][nt][3])
                        : "r"(af[mt][0]), "r"(af[mt][1]), "r"(af[mt][2]), "r"(af[mt][3]),
                          "r"(bf[nt][0]), "r"(bf[nt][1]));
                }
        }
        __syncthreads();
    }

    // ---- second GEMM: z @ Ws ----
    const int T2 = K2 >> 5;
    for (int q = 0; q < T2; q++) {
        uint4 a0 = make_uint4(0,0,0,0);
        if (gm < N_NODES)
            a0 = *(const uint4*)&A2[(size_t)gm * K2 + q*32 + ak];
        uint4 b0 = *(const uint4*)&W2[(size_t)(q*32 + brow) * DIM + bcol];
        uint4 b1 = *(const uint4*)&W2[(size_t)(q*32 + 16 + brow) * DIM + bcol];
        __syncthreads();
        *(uint4*)&Ag[0][arow][ak] = a0;
        *(uint4*)&Bg[0][brow][bcol]      = b0;
        *(uint4*)&Bg[0][16 + brow][bcol] = b1;
        __syncthreads();

        #pragma unroll
        for (int sub = 0; sub < 2; sub++) {
            const int kc = sub * 16;
            unsigned af[2][4];
            #pragma unroll
            for (int mt = 0; mt < 2; mt++) {
                const __half* p = &Ag[0][wm + mt*16 + (lane & 15)][kc + ((lane >> 4) << 3)];
                unsigned addr = (unsigned)__cvta_generic_to_shared(p);
                asm volatile("ldmatrix.sync.aligned.m8n8.x4.shared.b16 {%0,%1,%2,%3}, [%4];"
                    : "=r"(af[mt][0]), "=r"(af[mt][1]), "=r"(af[mt][2]), "=r"(af[mt][3])
                    : "r"(addr));
            }
            unsigned bf[4][2];
            #pragma unroll
            for (int qq = 0; qq < 2; qq++) {
                const __half* p = &Bg[0][kc + (lane & 15)][wn + qq*16 + ((lane >> 4) << 3)];
                unsigned addr = (unsigned)__cvta_generic_to_shared(p);
                asm volatile("ldmatrix.sync.aligned.m8n8.x4.trans.shared.b16 {%0,%1,%2,%3}, [%4];"
                    : "=r"(bf[qq*2][0]), "=r"(bf[qq*2][1]), "=r"(bf[qq*2+1][0]), "=r"(bf[qq*2+1][1])
                    : "r"(addr));
            }
            #pragma unroll
            for (int mt = 0; mt < 2; mt++)
                #pragma unroll
                for (int nt = 0; nt < 4; nt++) {
                    asm volatile(
                        "mma.sync.aligned.m16n8k16.row.col.f32.f16.f16.f32 "
                        "{%0,%1,%2,%3}, {%4,%5,%6,%7}, {%8,%9}, {%0,%1,%2,%3};"
                        : "+f"(acc[mt][nt][0]), "+f"(acc[mt][nt][1]),
                          "+f"(acc[mt][nt][2]), "+f"(acc[mt][nt][3])
                        : "r"(af[mt][0]), "r"(af[mt][1]), "r"(af[mt][2]), "r"(af[mt][3]),
                          "r"(bf[nt][0]), "r"(bf[nt][1]));
                }
        }
        __syncthreads();
    }

    // ---- epilogue 1: zi-tile = silu(acc + bs) -> R (fp32) + As (fp16) ----
    #pragma unroll
    for (int mt = 0; mt < 2; mt++) {
        #pragma unroll
        for (int nt = 0; nt < 4; nt++) {
            int col = wn + nt*8 + 2*t4;
            float b0 = bs[col], b1 = bs[col + 1];
            #pragma unroll
            for (int h = 0; h < 2; h++) {
                int rl = wm + mt*16 + g4 + h*8;
                float ox = silu_f(acc[mt][nt][h*2 + 0] + b0);
                float oy = silu_f(acc[mt][nt][h*2 + 1] + b1);
                R[rl][col] = ox; R[rl][col + 1] = oy;
                *(__half2*)&As[rl][col] = __floats2half2_rn(ox, oy);
            }
        }
    }
    __syncthreads();

    // ---- phase 2: 3x onsite blocks ----
    const int rw = t >> 1, cw = (t & 1) * 64;
    for (int j = 0; j < 3; j++) {
        const __half* Wa = WaBase + j * DIM * DIM;
        const __half* Wb = WbBase + j * DIM * DIM;
        const float*  ba = baBase + j * DIM;
        const float*  bb = bbBase + j * DIM;

        #pragma unroll
        for (int i = 0; i < 8; i++)
            *(uint4*)&Ws[rw][cw + i*8] = *(const uint4*)&Wa[rw * DIM + cw + i*8];
        __syncthreads();

        #pragma unroll
        for (int mt = 0; mt < 2; mt++)
            #pragma unroll
            for (int nt = 0; nt < 4; nt++)
                #pragma unroll
                for (int i = 0; i < 4; i++) acc[mt][nt][i] = 0.0f;

        #pragma unroll
        for (int kc = 0; kc < 128; kc += 16) {
            unsigned af[2][4];
            #pragma unroll
            for (int mt = 0; mt < 2; mt++) {
                const __half* p = &As[wm + mt*16 + (lane & 15)][kc + ((lane >> 4) << 3)];
                unsigned addr = (unsigned)__cvta_generic_to_shared(p);
                asm volatile("ldmatrix.sync.aligned.m8n8.x4.shared.b16 {%0,%1,%2,%3}, [%4];"
                    : "=r"(af[mt][0]), "=r"(af[mt][1]), "=r"(af[mt][2]), "=r"(af[mt][3])
                    : "r"(addr));
            }
            unsigned bf[4][2];
            #pragma unroll
            for (int q = 0; q < 2; q++) {
                const __half* p = &Ws[kc + (lane & 15)][wn + q*16 + ((lane >> 4) << 3)];
                unsigned addr = (unsigned)__cvta_generic_to_shared(p);
                asm volatile("ldmatrix.sync.aligned.m8n8.x4.trans.shared.b16 {%0,%1,%2,%3}, [%4];"
                    : "=r"(bf[q*2][0]), "=r"(bf[q*2][1]), "=r"(bf[q*2+1][0]), "=r"(bf[q*2+1][1])
                    : "r"(addr));
            }
            #pragma unroll
            for (int mt = 0; mt < 2; mt++)
                #pragma unroll
                for (int nt = 0; nt < 4; nt++) {
                    asm volatile(
                        "mma.sync.aligned.m16n8k16.row.col.f32.f16.f16.f32 "
                        "{%0,%1,%2,%3}, {%4,%5,%6,%7}, {%8,%9}, {%0,%1,%2,%3};"
                        : "+f"(acc[mt][nt][0]), "+f"(acc[mt][nt][1]),
                          "+f"(acc[mt][nt][2]), "+f"(acc[mt][nt][3])
                        : "r"(af[mt][0]), "r"(af[mt][1]), "r"(af[mt][2]), "r"(af[mt][3]),
                          "r"(bf[nt][0]), "r"(bf[nt][1]));
                }
        }
        __syncthreads();

        #pragma unroll
        for (int mt = 0; mt < 2; mt++) {
            #pragma unroll
            for (int nt = 0; nt < 4; nt++) {
                int col = wn + nt*8 + 2*t4;
                float b0 = ba[col], b1 = ba[col + 1];
                int r0 = wm + mt*16 + g4;
                *(__half2*)&As[r0][col] =
                    __floats2half2_rn(silu_f(acc[mt][nt][0] + b0), silu_f(acc[mt][nt][1] + b1));
                *(__half2*)&As[r0 + 8][col] =
                    __floats2half2_rn(silu_f(acc[mt][nt][2] + b0), silu_f(acc[mt][nt][3] + b1));
            }
        }
        #pragma unroll
        for (int i = 0; i < 8; i++)
            *(uint4*)&Ws[rw][cw + i*8] = *(const uint4*)&Wb[rw * DIM + cw + i*8];
        __syncthreads();

        #pragma unroll
        for (int mt = 0; mt < 2; mt++)
            #pragma unroll
            for (int nt = 0; nt < 4; nt++)
                #pragma unroll
                for (int i = 0; i < 4; i++) acc[mt][nt][i] = 0.0f;

        #pragma unroll
        for (int kc = 0; kc < 128; kc += 16) {
            unsigned af[2][4];
            #pragma unroll
            for (int mt = 0; mt < 2; mt++) {
                const __half* p = &As[wm + mt*16 + (lane & 15)][kc + ((lane >> 4) << 3)];
                unsigned addr = (unsigned)__cvta_generic_to_shared(p);
                asm volatile("ldmatrix.sync.aligned.m8n8.x4.shared.b16 {%0,%1,%2,%3}, [%4];"
                    : "=r"(af[mt][0]), "=r"(af[mt][1]), "=r"(af[mt][2]), "=r"(af[mt][3])
                    : "r"(addr));
            }
            unsigned bf[4][2];
            #pragma unroll
            for (int q = 0; q < 2; q++) {
                const __half* p = &Ws[kc + (lane & 15)][wn + q*16 + ((lane >> 4) << 3)];
                unsigned addr = (unsigned)__cvta_generic_to_shared(p);
                asm volatile("ldmatrix.sync.aligned.m8n8.x4.trans.shared.b16 {%0,%1,%2,%3}, [%4];"
                    : "=r"(bf[q*2][0]), "=r"(bf[q*2][1]), "=r"(bf[q*2+1][0]), "=r"(bf[q*2+1][1])
                    : "r"(addr));
            }
            #pragma unroll
            for (int mt = 0; mt < 2; mt++)
                #pragma unroll
                for (int nt = 0; nt < 4; nt++) {
                    asm volatile(
                        "mma.sync.aligned.m16n8k16.row.col.f32.f16.f16.f32 "
                        "{%0,%1,%2,%3}, {%4,%5,%6,%7}, {%8,%9}, {%0,%1,%2,%3};"
                        : "+f"(acc[mt][nt][0]), "+f"(acc[mt][nt][1]),
                          "+f"(acc[mt][nt][2]), "+f"(acc[mt][nt][3])
                        : "r"(af[mt][0]), "r"(af[mt][1]), "r"(af[mt][2]), "r"(af[mt][3]),
                          "r"(bf[nt][0]), "r"(bf[nt][1]));
                }
        }
        __syncthreads();

        #pragma unroll
        for (int mt = 0; mt < 2; mt++) {
            #pragma unroll
            for (int nt = 0; nt < 4; nt++) {
                int col = wn + nt*8 + 2*t4;
                float b0 = bb[col], b1 = bb[col + 1];
                #pragma unroll
                for (int h = 0; h < 2; h++) {
                    int rl = wm + mt*16 + g4 + h*8;
                    float2 o;
                    o.x = acc[mt][nt][h*2 + 0] + b0 + R[rl][col];
                    o.y = acc[mt][nt][h*2 + 1] + b1 + R[rl][col + 1];
                    if (j < 2) {
                        R[rl][col] = o.x; R[rl][col + 1] = o.y;
                        *(__half2*)&As[rl][col] = __floats2half2_rn(o.x, o.y);
                    } else {
                        int row = m0 + rl;
                        if (row < N_NODES) {
                            if (LAYER == 0) {
                                *(__half2*)&zih_out[(size_t)row * DIM + col] =
                                    __floats2half2_rn(o.x, o.y);
                                *(float2*)&out[(size_t)N_NODES * DIM + (size_t)row * 2 * DIM + col] = o;
                            } else {
                                *(float2*)&out[(size_t)row * DIM + col] = o;
                                *(float2*)&out[(size_t)N_NODES * DIM + (size_t)row * 2 * DIM + DIM + col] = o;
                            }
                        }
                    }
                }
            }
        }
        __syncthreads();
    }
}

// ---------------- host driver ----------------
extern "C" void kernel_launch(void* const* d_in, const int* in_sizes, int n_in,
                              void* d_out, int out_size)
{
    const int*   species = (const int*)  d_in[0];
    const int*   esrc    = (const int*)  d_in[1];
    const int*   edst    = (const int*)  d_in[2];
    const float* dist    = (const float*)d_in[3];
    const float* swp     = (const float*)d_in[4];
    const float* Z       = (const float*)d_in[5];
    const float* Ws0     = (const float*)d_in[6];
    const float* bs0     = (const float*)d_in[7];
    const float* V0      = (const float*)d_in[8];
    const float* Ws1     = (const float*)d_in[9];
    const float* bs1     = (const float*)d_in[10];
    const float* V1      = (const float*)d_in[11];
    const float* Won_a   = (const float*)d_in[12];
    const float* bon_a   = (const float*)d_in[13];
    const float* Won_b   = (const float*)d_in[14];
    const float* bon_b   = (const float*)d_in[15];
    float* out = (float*)d_out;

    __half *Ah, *Vh0, *Vh1, *z16h, *zih, *Ws0h, *Ws1h, *Wah, *Wbh;
    cudaGetSymbolAddress((void**)&Ah,    g_A);
    cudaGetSymbolAddress((void**)&Vh0,   g_Vh0);
    cudaGetSymbolAddress((void**)&Vh1,   g_Vh1);
    cudaGetSymbolAddress((void**)&z16h,  g_z16h);
    cudaGetSymbolAddress((void**)&zih,   g_zih);
    cudaGetSymbolAddress((void**)&Ws0h,  g_Ws0h);
    cudaGetSymbolAddress((void**)&Ws1h,  g_Ws1h);
    cudaGetSymbolAddress((void**)&Wah,   g_Wah);
    cudaGetSymbolAddress((void**)&Wbh,   g_Wbh);

    const int MB64 = (N_NODES + 63) / 64;       // 313
    const int NBK = (N_NODES + 7) / 8;
    const int PREP_N = N_NODES * 32;            // 640000 >= N_EDGES

    const int NODE_SMEM = 17408 + 34816 + 64 * DIM * 4;   // 84992
    static int attr_done = 0;
    if (!attr_done) {
        cudaFuncSetAttribute(k_nodeP<0>, cudaFuncAttributeMaxDynamicSharedMemorySize, NODE_SMEM);
        cudaFuncSetAttribute(k_nodeP<1>, cudaFuncAttributeMaxDynamicSharedMemorySize, NODE_SMEM);
        attr_done = 1;
    }

    // ---- preprocessing (conversions + padded-CSR fill in one launch) ----
    k_prep<<<(PREP_N + 255) / 256, 256>>>(species, Z, V0, V1, Ws0, Ws1,
                                          Won_a, Won_b, esrc, edst, dist, swp);

    // ---- layer 0 ----
    k_edgeT0<<<NBK, 256>>>();
    k_nodeP<0><<<MB64, 256, NODE_SMEM>>>(Ah, Vh0, z16h, Ws0h, bs0,
        Wah + 0*3*DIM*DIM, bon_a + 0*3*DIM, Wbh + 0*3*DIM*DIM, bon_b + 0*3*DIM,
        zih, out, KT0, 32);

    // ---- layer 1 ----
    k_edgeT1<<<NBK, 256>>>();
    k_nodeP<1><<<MB64, 256, NODE_SMEM>>>(Ah, Vh1, zih, Ws1h, bs1,
        Wah + 1*3*DIM*DIM, bon_a + 1*3*DIM, Wbh + 1*3*DIM*DIM, bon_b + 1*3*DIM,
        zih, out, KT1, DIM);
}

// round 14
// speedup vs baseline: 1.1009x; 1.1009x over previous
#include <cuda_runtime.h>
#include <cuda_fp16.h>
#include <math.h>

#define N_NODES 20000
#define N_EDGES 400000
#define DIM 128
#define NB 16
#define ZD 16
#define NLAYERS 2
#define KT1 (NB*DIM)   // 2048
#define KT0 (NB*ZD)    // 256
#define SCAN_BLKS ((N_NODES + 255) / 256)   // 79

// ---------------- device scratch (static, no allocations) ----------------
__device__ __half g_A[(size_t)N_NODES*KT1];     // aggregated T rows (fp16)
__device__ __half g_z16h[N_NODES*32];           // layer0 features, padded K2=32
__device__ __half g_zih[N_NODES*DIM];           // fp16 layer0 output
__device__ __half g_Vh0[KT0*DIM];               // V0.reshape(-1,128) fp16
__device__ __half g_Vh1[KT1*DIM];               // V1.reshape(-1,128) fp16
__device__ __half g_Ws0h[32*DIM];               // Ws0 padded to 32 rows, fp16
__device__ __half g_Ws1h[DIM*DIM];              // Ws1 fp16
__device__ __half g_Wah[NLAYERS*3*DIM*DIM];     // onsite Wa fp16
__device__ __half g_Wbh[NLAYERS*3*DIM*DIM];     // onsite Wb fp16

// CSR by src. g_degS starts zero (module load); k_scan3 re-zeroes each run.
__device__ int   g_degS[N_NODES], g_offS[N_NODES+1], g_curS[N_NODES];
__device__ int   g_part[128];
__device__ int   g_dstS[N_EDGES];
__device__ float g_distS[N_EDGES];
__device__ float g_swS[N_EDGES];

__device__ __forceinline__ float silu_f(float x) {
    return x / (1.0f + __expf(-x));
}

// ---------------- merged preprocessing (+ degree count) -------------------
__global__ void k_prep(const int* __restrict__ species, const float* __restrict__ Z,
                       const float* __restrict__ V0, const float* __restrict__ V1,
                       const float* __restrict__ Ws0, const float* __restrict__ Ws1,
                       const float* __restrict__ Wa, const float* __restrict__ Wb,
                       const int* __restrict__ esrc)
{
    int t = blockIdx.x * blockDim.x + threadIdx.x;
    if (t < N_NODES * 32) {
        int n = t >> 5, c = t & 31;
        g_z16h[t] = __float2half(c < ZD ? Z[species[n] * ZD + c] : 0.0f);
    }
    if (t < KT1 * DIM) g_Vh1[t] = __float2half(V1[t]);
    if (t < KT0 * DIM) g_Vh0[t] = __float2half(V0[t]);
    if (t < NLAYERS * 3 * DIM * DIM) {
        g_Wah[t] = __float2half(Wa[t]);
        g_Wbh[t] = __float2half(Wb[t]);
    }
    if (t < 32 * DIM) {
        int r = t >> 7;
        g_Ws0h[t] = __float2half(r < ZD ? Ws0[t] : 0.0f);
    }
    if (t < DIM * DIM) g_Ws1h[t] = __float2half(Ws1[t]);
    if (t < N_EDGES) atomicAdd(&g_degS[esrc[t]], 1);   // degS zero on entry
}

// ---------------- parallel scan ----------------
__global__ void k_scan1() {
    __shared__ int s[256];
    int t = threadIdx.x, idx = blockIdx.x * 256 + t;
    s[t] = (idx < N_NODES) ? g_degS[idx] : 0;
    __syncthreads();
    #pragma unroll
    for (int d = 128; d > 0; d >>= 1) {
        if (t < d) s[t] += s[t + d];
        __syncthreads();
    }
    if (t == 0) g_part[blockIdx.x] = s[0];
}
__global__ void k_scan2() {
    __shared__ int s[128];
    int t = threadIdx.x;
    int v = (t < SCAN_BLKS) ? g_part[t] : 0;
    s[t] = v;
    __syncthreads();
    #pragma unroll
    for (int d = 1; d < 128; d <<= 1) {
        int x = (t >= d) ? s[t - d] : 0;
        __syncthreads();
        s[t] += x;
        __syncthreads();
    }
    if (t < SCAN_BLKS) g_part[t] = s[t] - v;
    if (t == 127) g_offS[N_NODES] = s[127];
}
__global__ void k_scan3() {
    __shared__ int s[256];
    int t = threadIdx.x, idx = blockIdx.x * 256 + t;
    int v = (idx < N_NODES) ? g_degS[idx] : 0;
    s[t] = v;
    __syncthreads();
    #pragma unroll
    for (int d = 1; d < 256; d <<= 1) {
        int x = (t >= d) ? s[t - d] : 0;
        __syncthreads();
        s[t] += x;
        __syncthreads();
    }
    int excl = s[t] - v + g_part[blockIdx.x];
    if (idx < N_NODES) {
        g_offS[idx] = excl;
        g_curS[idx] = excl;
        g_degS[idx] = 0;        // self-clean for next replay
    }
}
__global__ void k_fillS(const int* __restrict__ esrc, const int* __restrict__ edst,
                        const float* __restrict__ dist, const float* __restrict__ sw) {
    int e = blockIdx.x * blockDim.x + threadIdx.x;
    if (e < N_EDGES) {
        int pos = atomicAdd(&g_curS[esrc[e]], 1);
        g_dstS[pos]  = edst[e];
        g_distS[pos] = dist[e];
        g_swS[pos]   = sw[e];
    }
}

// ---------------- edge aggregation via tensor cores -----------------------
// Layer 1: warp = (node, 64-dim half). 2 warps per node, 4 nodes per block.
__global__ __launch_bounds__(256, 4) void k_edgeT1() {
    __shared__ __half SA[8][16][24];    // [warp][basis][edge-slot]
    __shared__ __half SB[8][16][72];    // [warp][edge-slot][64 dims + pad]

    const int warp = threadIdx.x >> 5;
    const int lane = threadIdx.x & 31;
    const int n    = blockIdx.x * 4 + (warp >> 1);
    const int half = warp & 1;
    if (n >= N_NODES) return;
    const int p0 = g_offS[n], p1 = g_offS[n + 1];

    float acc[8][4];
    #pragma unroll
    for (int nt = 0; nt < 8; nt++)
        #pragma unroll
        for (int i = 0; i < 4; i++) acc[nt][i] = 0.0f;

    const int el = lane & 15, hi = lane >> 4;
    const float sigma  = 0.8f / 15.0f;
    const float rsigma = 15.0f / 0.8f;
    const int dbase = half * 64;

    for (int c = p0; c < p1; c += 16) {
        const int p = c + el;
        const bool v = (p < p1);
        const int dst   = v ? g_dstS[p]  : 0;
        const float di  = v ? g_distS[p] : 1.0f;
        const float sw  = v ? g_swS[p]   : 0.0f;
        const float rinv = 1.0f / di;

        #pragma unroll
        for (int j = 0; j < 8; j++) {
            const float mu = 0.2f + (float)(hi * 8 + j) * sigma;
            const float x = (rinv - mu) * rsigma;
            SA[warp][hi * 8 + j][el] = __float2half(__expf(-0.5f * x * x) * sw);
        }
        // z tile: 16 rows x 64 halves; 4 rounds, 4 rows per round
        #pragma unroll
        for (int r4 = 0; r4 < 4; r4++) {
            const int row = r4 * 4 + (lane >> 3);
            const int col8 = (lane & 7) * 8;
            const int rdst = __shfl_sync(0xffffffffu, dst, row);
            *(uint4*)&SB[warp][row][col8] =
                *(const uint4*)&g_zih[(size_t)rdst * DIM + dbase + col8];
        }
        __syncwarp();

        unsigned af[4];
        {
            const __half* pA = &SA[warp][el][hi * 8];
            unsigned addr = (unsigned)__cvta_generic_to_shared(pA);
            asm volatile("ldmatrix.sync.aligned.m8n8.x4.shared.b16 {%0,%1,%2,%3}, [%4];"
                : "=r"(af[0]), "=r"(af[1]), "=r"(af[2]), "=r"(af[3]) : "r"(addr));
        }
        #pragma unroll
        for (int q = 0; q < 4; q++) {
            unsigned bf[2][2];
            const __half* pB = &SB[warp][el][q * 16 + hi * 8];
            unsigned addr = (unsigned)__cvta_generic_to_shared(pB);
            asm volatile("ldmatrix.sync.aligned.m8n8.x4.trans.shared.b16 {%0,%1,%2,%3}, [%4];"
                : "=r"(bf[0][0]), "=r"(bf[0][1]), "=r"(bf[1][0]), "=r"(bf[1][1])
                : "r"(addr));
            #pragma unroll
            for (int h = 0; h < 2; h++) {
                asm volatile(
                    "mma.sync.aligned.m16n8k16.row.col.f32.f16.f16.f32 "
                    "{%0,%1,%2,%3}, {%4,%5,%6,%7}, {%8,%9}, {%0,%1,%2,%3};"
                    : "+f"(acc[q*2+h][0]), "+f"(acc[q*2+h][1]),
                      "+f"(acc[q*2+h][2]), "+f"(acc[q*2+h][3])
                    : "r"(af[0]), "r"(af[1]), "r"(af[2]), "r"(af[3]),
                      "r"(bf[h][0]), "r"(bf[h][1]));
            }
        }
        __syncwarp();
    }

    const int g4 = lane >> 2, t4 = lane & 3;
    __half* Ap = g_A + (size_t)n * KT1 + dbase;
    #pragma unroll
    for (int nt = 0; nt < 8; nt++) {
        *(__half2*)&Ap[(size_t)g4 * DIM + nt*8 + 2*t4] =
            __floats2half2_rn(acc[nt][0], acc[nt][1]);
        *(__half2*)&Ap[(size_t)(g4 + 8) * DIM + nt*8 + 2*t4] =
            __floats2half2_rn(acc[nt][2], acc[nt][3]);
    }
}

__global__ __launch_bounds__(256) void k_edgeT0() {
    __shared__ __half SA[8][16][24];
    __shared__ __half SB[8][16][24];

    const int warp = threadIdx.x >> 5;
    const int lane = threadIdx.x & 31;
    const int n = blockIdx.x * 8 + warp;
    if (n >= N_NODES) return;
    const int p0 = g_offS[n], p1 = g_offS[n + 1];

    float acc[2][4];
    #pragma unroll
    for (int nt = 0; nt < 2; nt++)
        #pragma unroll
        for (int i = 0; i < 4; i++) acc[nt][i] = 0.0f;

    const int el = lane & 15, hi = lane >> 4;
    const float sigma  = 0.8f / 15.0f;
    const float rsigma = 15.0f / 0.8f;

    for (int c = p0; c < p1; c += 16) {
        const int p = c + el;
        const bool v = (p < p1);
        const int dst   = v ? g_dstS[p]  : 0;
        const float di  = v ? g_distS[p] : 1.0f;
        const float sw  = v ? g_swS[p]   : 0.0f;
        const float rinv = 1.0f / di;

        #pragma unroll
        for (int j = 0; j < 8; j++) {
            const float mu = 0.2f + (float)(hi * 8 + j) * sigma;
            const float x = (rinv - mu) * rsigma;
            SA[warp][hi * 8 + j][el] = __float2half(__expf(-0.5f * x * x) * sw);
        }
        {
            const int row = lane >> 1;
            const int rdst = __shfl_sync(0xffffffffu, dst, row);
            *(uint4*)&SB[warp][row][(lane & 1) * 8] =
                *(const uint4*)&g_z16h[rdst * 32 + (lane & 1) * 8];
        }
        __syncwarp();

        unsigned af[4];
        {
            const __half* pA = &SA[warp][el][hi * 8];
            unsigned addr = (unsigned)__cvta_generic_to_shared(pA);
            asm volatile("ldmatrix.sync.aligned.m8n8.x4.shared.b16 {%0,%1,%2,%3}, [%4];"
                : "=r"(af[0]), "=r"(af[1]), "=r"(af[2]), "=r"(af[3]) : "r"(addr));
        }
        unsigned bf[2][2];
        {
            const __half* pB = &SB[warp][el][hi * 8];
            unsigned addr = (unsigned)__cvta_generic_to_shared(pB);
            asm volatile("ldmatrix.sync.aligned.m8n8.x4.trans.shared.b16 {%0,%1,%2,%3}, [%4];"
                : "=r"(bf[0][0]), "=r"(bf[0][1]), "=r"(bf[1][0]), "=r"(bf[1][1])
                : "r"(addr));
        }
        #pragma unroll
        for (int h = 0; h < 2; h++) {
            asm volatile(
                "mma.sync.aligned.m16n8k16.row.col.f32.f16.f16.f32 "
                "{%0,%1,%2,%3}, {%4,%5,%6,%7}, {%8,%9}, {%0,%1,%2,%3};"
                : "+f"(acc[h][0]), "+f"(acc[h][1]), "+f"(acc[h][2]), "+f"(acc[h][3])
                : "r"(af[0]), "r"(af[1]), "r"(af[2]), "r"(af[3]),
                  "r"(bf[h][0]), "r"(bf[h][1]));
        }
        __syncwarp();
    }

    const int g4 = lane >> 2, t4 = lane & 3;
    __half* Ap = g_A + (size_t)n * KT0;
    #pragma unroll
    for (int nt = 0; nt < 2; nt++) {
        *(__half2*)&Ap[g4 * ZD + nt*8 + 2*t4] =
            __floats2half2_rn(acc[nt][0], acc[nt][1]);
        *(__half2*)&Ap[(g4 + 8) * ZD + nt*8 + 2*t4] =
            __floats2half2_rn(acc[nt][2], acc[nt][3]);
    }
}

// ---------------- fused node pipeline -------------------------------------
#define CPA16(dst, src, bytes) \
    asm volatile("cp.async.cg.shared.global [%0], [%1], 16, %2;" \
                 :: "r"(dst), "l"(src), "r"(bytes))

template<int LAYER>
__global__ __launch_bounds__(256) void k_nodeP(
    const __half* __restrict__ A, const __half* __restrict__ B,
    const __half* __restrict__ A2, const __half* __restrict__ W2,
    const float* __restrict__ bs,
    const __half* __restrict__ WaBase, const float* __restrict__ baBase,
    const __half* __restrict__ WbBase, const float* __restrict__ bbBase,
    __half* __restrict__ zih_out, float* __restrict__ out,
    int K, int K2)
{
    extern __shared__ char sm[];
    __half (*As)[136] = (__half(*)[136])sm;                       // 64x136
    __half (*Ws)[136] = (__half(*)[136])(sm + 17408);             // 128x136
    float  (*R)[DIM]  = (float (*)[DIM])(sm + 52224);             // 64x128 fp32
    __half (*Ag)[64][40]  = (__half(*)[64][40]) (sm + 17408);
    __half (*Bg)[32][136] = (__half(*)[32][136])(sm + 17408 + 10240);

    const int t = threadIdx.x;
    const int warp = t >> 5, lane = t & 31;
    const int wm = (warp & 1) * 32, wn = (warp >> 1) * 32;
    const int m0 = blockIdx.x * 64;
    const int g4 = lane >> 2, t4 = lane & 3;

    const int arow = t >> 2, ak = (t & 3) * 8;
    const int brow = t >> 4, bcol = (t & 15) * 8;
    const int gm = m0 + arow;
    const int apred = (gm < N_NODES) ? 16 : 0;
    const __half* Abase = &A[(size_t)gm * K];

    float acc[2][4][4];
    #pragma unroll
    for (int mt = 0; mt < 2; mt++)
        #pragma unroll
        for (int nt = 0; nt < 4; nt++)
            #pragma unroll
            for (int i = 0; i < 4; i++) acc[mt][nt][i] = 0.0f;

    const int T = K >> 5;

    {
        unsigned da = (unsigned)__cvta_generic_to_shared(&Ag[0][arow][ak]);
        CPA16(da, Abase + ak, apred);
        unsigned db0 = (unsigned)__cvta_generic_to_shared(&Bg[0][brow][bcol]);
        unsigned db1 = (unsigned)__cvta_generic_to_shared(&Bg[0][16 + brow][bcol]);
        CPA16(db0, &B[(size_t)brow * DIM + bcol], 16);
        CPA16(db1, &B[(size_t)(16 + brow) * DIM + bcol], 16);
        asm volatile("cp.async.commit_group;");
    }

    for (int tt = 0; tt < T; tt++) {
        if (tt + 1 < T) {
            const int buf = (tt + 1) & 1, k0 = (tt + 1) * 32;
            unsigned da = (unsigned)__cvta_generic_to_shared(&Ag[buf][arow][ak]);
            CPA16(da, Abase + k0 + ak, apred);
            unsigned db0 = (unsigned)__cvta_generic_to_shared(&Bg[buf][brow][bcol]);
            unsigned db1 = (unsigned)__cvta_generic_to_shared(&Bg[buf][16 + brow][bcol]);
            CPA16(db0, &B[(size_t)(k0 + brow) * DIM + bcol], 16);
            CPA16(db1, &B[(size_t)(k0 + 16 + brow) * DIM + bcol], 16);
            asm volatile("cp.async.commit_group;");
            asm volatile("cp.async.wait_group 1;");
        } else {
            asm volatile("cp.async.wait_group 0;");
        }
        __syncthreads();

        const int buf = tt & 1;
        #pragma unroll
        for (int sub = 0; sub < 2; sub++) {
            const int kc = sub * 16;
            unsigned af[2][4];
            #pragma unroll
            for (int mt = 0; mt < 2; mt++) {
                const __half* p = &Ag[buf][wm + mt*16 + (lane & 15)][kc + ((lane >> 4) << 3)];
                unsigned addr = (unsigned)__cvta_generic_to_shared(p);
                asm volatile("ldmatrix.sync.aligned.m8n8.x4.shared.b16 {%0,%1,%2,%3}, [%4];"
                    : "=r"(af[mt][0]), "=r"(af[mt][1]), "=r"(af[mt][2]), "=r"(af[mt][3])
                    : "r"(addr));
            }
            unsigned bf[4][2];
            #pragma unroll
            for (int q = 0; q < 2; q++) {
                const __half* p = &Bg[buf][kc + (lane & 15)][wn + q*16 + ((lane >> 4) << 3)];
                unsigned addr = (unsigned)__cvta_generic_to_shared(p);
                asm volatile("ldmatrix.sync.aligned.m8n8.x4.trans.shared.b16 {%0,%1,%2,%3}, [%4];"
                    : "=r"(bf[q*2][0]), "=r"(bf[q*2][1]), "=r"(bf[q*2+1][0]), "=r"(bf[q*2+1][1])
                    : "r"(addr));
            }
            #pragma unroll
            for (int mt = 0; mt < 2; mt++)
                #pragma unroll
                for (int nt = 0; nt < 4; nt++) {
                    asm volatile(
                        "mma.sync.aligned.m16n8k16.row.col.f32.f16.f16.f32 "
                        "{%0,%1,%2,%3}, {%4,%5,%6,%7}, {%8,%9}, {%0,%1,%2,%3};"
                        : "+f"(acc[mt][nt][0]), "+f"(acc[mt][nt][1]),
                          "+f"(acc[mt][nt][2]), "+f"(acc[mt][nt][3])
                        : "r"(af[mt][0]), "r"(af[mt][1]), "r"(af[mt][2]), "r"(af[mt][3]),
                          "r"(bf[nt][0]), "r"(bf[nt][1]));
                }
        }
        __syncthreads();
    }

    // ---- second GEMM: z @ Ws ----
    const int T2 = K2 >> 5;
    for (int q = 0; q < T2; q++) {
        uint4 a0 = make_uint4(0,0,0,0);
        if (gm < N_NODES)
            a0 = *(const uint4*)&A2[(size_t)gm * K2 + q*32 + ak];
        uint4 b0 = *(const uint4*)&W2[(size_t)(q*32 + brow) * DIM + bcol];
        uint4 b1 = *(const uint4*)&W2[(size_t)(q*32 + 16 + brow) * DIM + bcol];
        __syncthreads();
        *(uint4*)&Ag[0][arow][ak] = a0;
        *(uint4*)&Bg[0][brow][bcol]      = b0;
        *(uint4*)&Bg[0][16 + brow][bcol] = b1;
        __syncthreads();

        #pragma unroll
        for (int sub = 0; sub < 2; sub++) {
            const int kc = sub * 16;
            unsigned af[2][4];
            #pragma unroll
            for (int mt = 0; mt < 2; mt++) {
                const __half* p = &Ag[0][wm + mt*16 + (lane & 15)][kc + ((lane >> 4) << 3)];
                unsigned addr = (unsigned)__cvta_generic_to_shared(p);
                asm volatile("ldmatrix.sync.aligned.m8n8.x4.shared.b16 {%0,%1,%2,%3}, [%4];"
                    : "=r"(af[mt][0]), "=r"(af[mt][1]), "=r"(af[mt][2]), "=r"(af[mt][3])
                    : "r"(addr));
            }
            unsigned bf[4][2];
            #pragma unroll
            for (int qq = 0; qq < 2; qq++) {
                const __half* p = &Bg[0][kc + (lane & 15)][wn + qq*16 + ((lane >> 4) << 3)];
                unsigned addr = (unsigned)__cvta_generic_to_shared(p);
                asm volatile("ldmatrix.sync.aligned.m8n8.x4.trans.shared.b16 {%0,%1,%2,%3}, [%4];"
                    : "=r"(bf[qq*2][0]), "=r"(bf[qq*2][1]), "=r"(bf[qq*2+1][0]), "=r"(bf[qq*2+1][1])
                    : "r"(addr));
            }
            #pragma unroll
            for (int mt = 0; mt < 2; mt++)
                #pragma unroll
                for (int nt = 0; nt < 4; nt++) {
                    asm volatile(
                        "mma.sync.aligned.m16n8k16.row.col.f32.f16.f16.f32 "
                        "{%0,%1,%2,%3}, {%4,%5,%6,%7}, {%8,%9}, {%0,%1,%2,%3};"
                        : "+f"(acc[mt][nt][0]), "+f"(acc[mt][nt][1]),
                          "+f"(acc[mt][nt][2]), "+f"(acc[mt][nt][3])
                        : "r"(af[mt][0]), "r"(af[mt][1]), "r"(af[mt][2]), "r"(af[mt][3]),
                          "r"(bf[nt][0]), "r"(bf[nt][1]));
                }
        }
        __syncthreads();
    }

    // ---- epilogue 1: zi-tile = silu(acc + bs) -> R (fp32) + As (fp16) ----
    #pragma unroll
    for (int mt = 0; mt < 2; mt++) {
        #pragma unroll
        for (int nt = 0; nt < 4; nt++) {
            int col = wn + nt*8 + 2*t4;
            float b0 = bs[col], b1 = bs[col + 1];
            #pragma unroll
            for (int h = 0; h < 2; h++) {
                int rl = wm + mt*16 + g4 + h*8;
                float ox = silu_f(acc[mt][nt][h*2 + 0] + b0);
                float oy = silu_f(acc[mt][nt][h*2 + 1] + b1);
                R[rl][col] = ox; R[rl][col + 1] = oy;
                *(__half2*)&As[rl][col] = __floats2half2_rn(ox, oy);
            }
        }
    }
    __syncthreads();

    // ---- phase 2: 3x onsite blocks ----
    const int rw = t >> 1, cw = (t & 1) * 64;
    for (int j = 0; j < 3; j++) {
        const __half* Wa = WaBase + j * DIM * DIM;
        const __half* Wb = WbBase + j * DIM * DIM;
        const float*  ba = baBase + j * DIM;
        const float*  bb = bbBase + j * DIM;

        #pragma unroll
        for (int i = 0; i < 8; i++)
            *(uint4*)&Ws[rw][cw + i*8] = *(const uint4*)&Wa[rw * DIM + cw + i*8];
        __syncthreads();

        #pragma unroll
        for (int mt = 0; mt < 2; mt++)
            #pragma unroll
            for (int nt = 0; nt < 4; nt++)
                #pragma unroll
                for (int i = 0; i < 4; i++) acc[mt][nt][i] = 0.0f;

        #pragma unroll
        for (int kc = 0; kc < 128; kc += 16) {
            unsigned af[2][4];
            #pragma unroll
            for (int mt = 0; mt < 2; mt++) {
                const __half* p = &As[wm + mt*16 + (lane & 15)][kc + ((lane >> 4) << 3)];
                unsigned addr = (unsigned)__cvta_generic_to_shared(p);
                asm volatile("ldmatrix.sync.aligned.m8n8.x4.shared.b16 {%0,%1,%2,%3}, [%4];"
                    : "=r"(af[mt][0]), "=r"(af[mt][1]), "=r"(af[mt][2]), "=r"(af[mt][3])
                    : "r"(addr));
            }
            unsigned bf[4][2];
            #pragma unroll
            for (int q = 0; q < 2; q++) {
                const __half* p = &Ws[kc + (lane & 15)][wn + q*16 + ((lane >> 4) << 3)];
                unsigned addr = (unsigned)__cvta_generic_to_shared(p);
                asm volatile("ldmatrix.sync.aligned.m8n8.x4.trans.shared.b16 {%0,%1,%2,%3}, [%4];"
                    : "=r"(bf[q*2][0]), "=r"(bf[q*2][1]), "=r"(bf[q*2+1][0]), "=r"(bf[q*2+1][1])
                    : "r"(addr));
            }
            #pragma unroll
            for (int mt = 0; mt < 2; mt++)
                #pragma unroll
                for (int nt = 0; nt < 4; nt++) {
                    asm volatile(
                        "mma.sync.aligned.m16n8k16.row.col.f32.f16.f16.f32 "
                        "{%0,%1,%2,%3}, {%4,%5,%6,%7}, {%8,%9}, {%0,%1,%2,%3};"
                        : "+f"(acc[mt][nt][0]), "+f"(acc[mt][nt][1]),
                          "+f"(acc[mt][nt][2]), "+f"(acc[mt][nt][3])
                        : "r"(af[mt][0]), "r"(af[mt][1]), "r"(af[mt][2]), "r"(af[mt][3]),
                          "r"(bf[nt][0]), "r"(bf[nt][1]));
                }
        }
        __syncthreads();

        #pragma unroll
        for (int mt = 0; mt < 2; mt++) {
            #pragma unroll
            for (int nt = 0; nt < 4; nt++) {
                int col = wn + nt*8 + 2*t4;
                float b0 = ba[col], b1 = ba[col + 1];
                int r0 = wm + mt*16 + g4;
                *(__half2*)&As[r0][col] =
                    __floats2half2_rn(silu_f(acc[mt][nt][0] + b0), silu_f(acc[mt][nt][1] + b1));
                *(__half2*)&As[r0 + 8][col] =
                    __floats2half2_rn(silu_f(acc[mt][nt][2] + b0), silu_f(acc[mt][nt][3] + b1));
            }
        }
        #pragma unroll
        for (int i = 0; i < 8; i++)
            *(uint4*)&Ws[rw][cw + i*8] = *(const uint4*)&Wb[rw * DIM + cw + i*8];
        __syncthreads();

        #pragma unroll
        for (int mt = 0; mt < 2; mt++)
            #pragma unroll
            for (int nt = 0; nt < 4; nt++)
                #pragma unroll
                for (int i = 0; i < 4; i++) acc[mt][nt][i] = 0.0f;

        #pragma unroll
        for (int kc = 0; kc < 128; kc += 16) {
            unsigned af[2][4];
            #pragma unroll
            for (int mt = 0; mt < 2; mt++) {
                const __half* p = &As[wm + mt*16 + (lane & 15)][kc + ((lane >> 4) << 3)];
                unsigned addr = (unsigned)__cvta_generic_to_shared(p);
                asm volatile("ldmatrix.sync.aligned.m8n8.x4.shared.b16 {%0,%1,%2,%3}, [%4];"
                    : "=r"(af[mt][0]), "=r"(af[mt][1]), "=r"(af[mt][2]), "=r"(af[mt][3])
                    : "r"(addr));
            }
            unsigned bf[4][2];
            #pragma unroll
            for (int q = 0; q < 2; q++) {
                const __half* p = &Ws[kc + (lane & 15)][wn + q*16 + ((lane >> 4) << 3)];
                unsigned addr = (unsigned)__cvta_generic_to_shared(p);
                asm volatile("ldmatrix.sync.aligned.m8n8.x4.trans.shared.b16 {%0,%1,%2,%3}, [%4];"
                    : "=r"(bf[q*2][0]), "=r"(bf[q*2][1]), "=r"(bf[q*2+1][0]), "=r"(bf[q*2+1][1])
                    : "r"(addr));
            }
            #pragma unroll
            for (int mt = 0; mt < 2; mt++)
                #pragma unroll
                for (int nt = 0; nt < 4; nt++) {
                    asm volatile(
                        "mma.sync.aligned.m16n8k16.row.col.f32.f16.f16.f32 "
                        "{%0,%1,%2,%3}, {%4,%5,%6,%7}, {%8,%9}, {%0,%1,%2,%3};"
                        : "+f"(acc[mt][nt][0]), "+f"(acc[mt][nt][1]),
                          "+f"(acc[mt][nt][2]), "+f"(acc[mt][nt][3])
                        : "r"(af[mt][0]), "r"(af[mt][1]), "r"(af[mt][2]), "r"(af[mt][3]),
                          "r"(bf[nt][0]), "r"(bf[nt][1]));
                }
        }
        __syncthreads();

        #pragma unroll
        for (int mt = 0; mt < 2; mt++) {
            #pragma unroll
            for (int nt = 0; nt < 4; nt++) {
                int col = wn + nt*8 + 2*t4;
                float b0 = bb[col], b1 = bb[col + 1];
                #pragma unroll
                for (int h = 0; h < 2; h++) {
                    int rl = wm + mt*16 + g4 + h*8;
                    float2 o;
                    o.x = acc[mt][nt][h*2 + 0] + b0 + R[rl][col];
                    o.y = acc[mt][nt][h*2 + 1] + b1 + R[rl][col + 1];
                    if (j < 2) {
                        R[rl][col] = o.x; R[rl][col + 1] = o.y;
                        *(__half2*)&As[rl][col] = __floats2half2_rn(o.x, o.y);
                    } else {
                        int row = m0 + rl;
                        if (row < N_NODES) {
                            if (LAYER == 0) {
                                *(__half2*)&zih_out[(size_t)row * DIM + col] =
                                    __floats2half2_rn(o.x, o.y);
                                *(float2*)&out[(size_t)N_NODES * DIM + (size_t)row * 2 * DIM + col] = o;
                            } else {
                                *(float2*)&out[(size_t)row * DIM + col] = o;
                                *(float2*)&out[(size_t)N_NODES * DIM + (size_t)row * 2 * DIM + DIM + col] = o;
                            }
                        }
                    }
                }
            }
        }
        __syncthreads();
    }
}

// ---------------- host driver ----------------
extern "C" void kernel_launch(void* const* d_in, const int* in_sizes, int n_in,
                              void* d_out, int out_size)
{
    const int*   species = (const int*)  d_in[0];
    const int*   esrc    = (const int*)  d_in[1];
    const int*   edst    = (const int*)  d_in[2];
    const float* dist    = (const float*)d_in[3];
    const float* swp     = (const float*)d_in[4];
    const float* Z       = (const float*)d_in[5];
    const float* Ws0     = (const float*)d_in[6];
    const float* bs0     = (const float*)d_in[7];
    const float* V0      = (const float*)d_in[8];
    const float* Ws1     = (const float*)d_in[9];
    const float* bs1     = (const float*)d_in[10];
    const float* V1      = (const float*)d_in[11];
    const float* Won_a   = (const float*)d_in[12];
    const float* bon_a   = (const float*)d_in[13];
    const float* Won_b   = (const float*)d_in[14];
    const float* bon_b   = (const float*)d_in[15];
    float* out = (float*)d_out;

    __half *Ah, *Vh0, *Vh1, *z16h, *zih, *Ws0h, *Ws1h, *Wah, *Wbh;
    cudaGetSymbolAddress((void**)&Ah,    g_A);
    cudaGetSymbolAddress((void**)&Vh0,   g_Vh0);
    cudaGetSymbolAddress((void**)&Vh1,   g_Vh1);
    cudaGetSymbolAddress((void**)&z16h,  g_z16h);
    cudaGetSymbolAddress((void**)&zih,   g_zih);
    cudaGetSymbolAddress((void**)&Ws0h,  g_Ws0h);
    cudaGetSymbolAddress((void**)&Ws1h,  g_Ws1h);
    cudaGetSymbolAddress((void**)&Wah,   g_Wah);
    cudaGetSymbolAddress((void**)&Wbh,   g_Wbh);

    const int MB64 = (N_NODES + 63) / 64;       // 313
    const int EB = (N_EDGES + 255) / 256;
    const int NBK = (N_NODES + 7) / 8;
    const int NBK2 = (N_NODES + 3) / 4;         // edgeT1: 2 warps per node
    const int PREP_N = N_NODES * 32;            // 640000 >= N_EDGES

    const int NODE_SMEM = 17408 + 34816 + 64 * DIM * 4;   // 84992
    static int attr_done = 0;
    if (!attr_done) {
        cudaFuncSetAttribute(k_nodeP<0>, cudaFuncAttributeMaxDynamicSharedMemorySize, NODE_SMEM);
        cudaFuncSetAttribute(k_nodeP<1>, cudaFuncAttributeMaxDynamicSharedMemorySize, NODE_SMEM);
        attr_done = 1;
    }

    // ---- preprocessing ----
    k_prep<<<(PREP_N + 255) / 256, 256>>>(species, Z, V0, V1, Ws0, Ws1, Won_a, Won_b, esrc);
    k_scan1<<<SCAN_BLKS, 256>>>();
    k_scan2<<<1, 128>>>();
    k_scan3<<<SCAN_BLKS, 256>>>();
    k_fillS<<<EB, 256>>>(esrc, edst, dist, swp);

    // ---- layer 0 ----
    k_edgeT0<<<NBK, 256>>>();
    k_nodeP<0><<<MB64, 256, NODE_SMEM>>>(Ah, Vh0, z16h, Ws0h, bs0,
        Wah + 0*3*DIM*DIM, bon_a + 0*3*DIM, Wbh + 0*3*DIM*DIM, bon_b + 0*3*DIM,
        zih, out, KT0, 32);

    // ---- layer 1 ----
    k_edgeT1<<<NBK2, 256>>>();
    k_nodeP<1><<<MB64, 256, NODE_SMEM>>>(Ah, Vh1, zih, Ws1h, bs1,
        Wah + 1*3*DIM*DIM, bon_a + 1*3*DIM, Wbh + 1*3*DIM*DIM, bon_b + 1*3*DIM,
        zih, out, KT1, DIM);
}

// round 15
// speedup vs baseline: 1.1060x; 1.0046x over previous
#include <cuda_runtime.h>
#include <cuda_fp16.h>
#include <math.h>

#define N_NODES 20000
#define N_EDGES 400000
#define DIM 128
#define NB 16
#define ZD 16
#define NLAYERS 2
#define KT1 (NB*DIM)   // 2048
#define KT0 (NB*ZD)    // 256
#define SCAN_BLKS ((N_NODES + 255) / 256)   // 79

// ---------------- device scratch (static, no allocations) ----------------
__device__ __half g_A[(size_t)N_NODES*KT1];     // aggregated T rows (fp16)
__device__ __half g_z16h[N_NODES*32];           // layer0 features, padded K2=32
__device__ __half g_zih[N_NODES*DIM];           // fp16 layer0 output
__device__ __half g_Vh0[KT0*DIM];               // V0.reshape(-1,128) fp16
__device__ __half g_Vh1[KT1*DIM];               // V1.reshape(-1,128) fp16
__device__ __half g_Ws0h[32*DIM];               // Ws0 padded to 32 rows, fp16
__device__ __half g_Ws1h[DIM*DIM];              // Ws1 fp16
__device__ __half g_Wah[NLAYERS*3*DIM*DIM];     // onsite Wa fp16
__device__ __half g_Wbh[NLAYERS*3*DIM*DIM];     // onsite Wb fp16

// CSR by src. g_degS starts zero (module load); k_scan3 re-zeroes each run.
__device__ int   g_degS[N_NODES], g_offS[N_NODES+1], g_curS[N_NODES];
__device__ int   g_part[128];
__device__ int   g_dstS[N_EDGES];
__device__ float g_distS[N_EDGES];
__device__ float g_swS[N_EDGES];

__device__ __forceinline__ float silu_f(float x) {
    return x / (1.0f + __expf(-x));
}

// exp(-(k+0.5)) for k = 0..6
#define EK0 0.60653066f
#define EK1 0.22313016f
#define EK2 0.082084998f
#define EK3 0.030197383f
#define EK4 0.011108997f
#define EK5 0.0040867714f
#define EK6 0.0015034391f

// ---------------- merged preprocessing (+ degree count) -------------------
__global__ void k_prep(const int* __restrict__ species, const float* __restrict__ Z,
                       const float* __restrict__ V0, const float* __restrict__ V1,
                       const float* __restrict__ Ws0, const float* __restrict__ Ws1,
                       const float* __restrict__ Wa, const float* __restrict__ Wb,
                       const int* __restrict__ esrc)
{
    int t = blockIdx.x * blockDim.x + threadIdx.x;
    if (t < N_NODES * 32) {
        int n = t >> 5, c = t & 31;
        g_z16h[t] = __float2half(c < ZD ? Z[species[n] * ZD + c] : 0.0f);
    }
    if (t < KT1 * DIM) g_Vh1[t] = __float2half(V1[t]);
    if (t < KT0 * DIM) g_Vh0[t] = __float2half(V0[t]);
    if (t < NLAYERS * 3 * DIM * DIM) {
        g_Wah[t] = __float2half(Wa[t]);
        g_Wbh[t] = __float2half(Wb[t]);
    }
    if (t < 32 * DIM) {
        int r = t >> 7;
        g_Ws0h[t] = __float2half(r < ZD ? Ws0[t] : 0.0f);
    }
    if (t < DIM * DIM) g_Ws1h[t] = __float2half(Ws1[t]);
    if (t < N_EDGES) atomicAdd(&g_degS[esrc[t]], 1);   // degS zero on entry
}

// ---------------- parallel scan ----------------
__global__ void k_scan1() {
    __shared__ int s[256];
    int t = threadIdx.x, idx = blockIdx.x * 256 + t;
    s[t] = (idx < N_NODES) ? g_degS[idx] : 0;
    __syncthreads();
    #pragma unroll
    for (int d = 128; d > 0; d >>= 1) {
        if (t < d) s[t] += s[t + d];
        __syncthreads();
    }
    if (t == 0) g_part[blockIdx.x] = s[0];
}
__global__ void k_scan2() {
    __shared__ int s[128];
    int t = threadIdx.x;
    int v = (t < SCAN_BLKS) ? g_part[t] : 0;
    s[t] = v;
    __syncthreads();
    #pragma unroll
    for (int d = 1; d < 128; d <<= 1) {
        int x = (t >= d) ? s[t - d] : 0;
        __syncthreads();
        s[t] += x;
        __syncthreads();
    }
    if (t < SCAN_BLKS) g_part[t] = s[t] - v;
    if (t == 127) g_offS[N_NODES] = s[127];
}
__global__ void k_scan3() {
    __shared__ int s[256];
    int t = threadIdx.x, idx = blockIdx.x * 256 + t;
    int v = (idx < N_NODES) ? g_degS[idx] : 0;
    s[t] = v;
    __syncthreads();
    #pragma unroll
    for (int d = 1; d < 256; d <<= 1) {
        int x = (t >= d) ? s[t - d] : 0;
        __syncthreads();
        s[t] += x;
        __syncthreads();
    }
    int excl = s[t] - v + g_part[blockIdx.x];
    if (idx < N_NODES) {
        g_offS[idx] = excl;
        g_curS[idx] = excl;
        g_degS[idx] = 0;        // self-clean for next replay
    }
}
__global__ void k_fillS(const int* __restrict__ esrc, const int* __restrict__ edst,
                        const float* __restrict__ dist, const float* __restrict__ sw) {
    int e = blockIdx.x * blockDim.x + threadIdx.x;
    if (e < N_EDGES) {
        int pos = atomicAdd(&g_curS[esrc[e]], 1);
        g_dstS[pos]  = edst[e];
        g_distS[pos] = dist[e];
        g_swS[pos]   = sw[e];
    }
}

// ---------------- edge aggregation via tensor cores -----------------------
__global__ __launch_bounds__(256) void k_edgeT1() {
    __shared__ __half SA[8][16][24];    // [warp][basis][edge-slot]
    __shared__ __half SB[8][16][136];   // [warp][edge-slot][dim]

    const int warp = threadIdx.x >> 5;
    const int lane = threadIdx.x & 31;
    const int n = blockIdx.x * 8 + warp;
    if (n >= N_NODES) return;
    const int p0 = g_offS[n], p1 = g_offS[n + 1];

    float acc[16][4];
    #pragma unroll
    for (int nt = 0; nt < 16; nt++)
        #pragma unroll
        for (int i = 0; i < 4; i++) acc[nt][i] = 0.0f;

    const int el = lane & 15, hi = lane >> 4;
    const float rsigma = 15.0f / 0.8f;

    for (int c = p0; c < p1; c += 16) {
        const int p = c + el;
        const bool v = (p < p1);
        const int dst   = v ? g_dstS[p]  : 0;
        const float di  = v ? g_distS[p] : 1.0f;
        const float sw  = v ? g_swS[p]   : 0.0f;
        const float rinv = 1.0f / di;

        // Gaussian recurrence: s_k = exp(-0.5 (v0-k)^2), 2 MUFU per lane
        {
            const float v0 = (rinv - 0.2f) * rsigma - (float)(hi * 8);
            float sv = __expf(-0.5f * v0 * v0) * sw;
            const float Bp = __expf(v0);
            SA[warp][hi * 8 + 0][el] = __float2half(sv);
            sv *= Bp * EK0; SA[warp][hi * 8 + 1][el] = __float2half(sv);
            sv *= Bp * EK1; SA[warp][hi * 8 + 2][el] = __float2half(sv);
            sv *= Bp * EK2; SA[warp][hi * 8 + 3][el] = __float2half(sv);
            sv *= Bp * EK3; SA[warp][hi * 8 + 4][el] = __float2half(sv);
            sv *= Bp * EK4; SA[warp][hi * 8 + 5][el] = __float2half(sv);
            sv *= Bp * EK5; SA[warp][hi * 8 + 6][el] = __float2half(sv);
            sv *= Bp * EK6; SA[warp][hi * 8 + 7][el] = __float2half(sv);
        }
        #pragma unroll
        for (int r2 = 0; r2 < 8; r2++) {
            const int row = r2 * 2 + hi;
            const int rdst = __shfl_sync(0xffffffffu, dst, row);
            *(uint4*)&SB[warp][row][el * 8] =
                *(const uint4*)&g_zih[(size_t)rdst * DIM + el * 8];
        }
        __syncwarp();

        unsigned af[4];
        {
            const __half* pA = &SA[warp][el][hi * 8];
            unsigned addr = (unsigned)__cvta_generic_to_shared(pA);
            asm volatile("ldmatrix.sync.aligned.m8n8.x4.shared.b16 {%0,%1,%2,%3}, [%4];"
                : "=r"(af[0]), "=r"(af[1]), "=r"(af[2]), "=r"(af[3]) : "r"(addr));
        }
        #pragma unroll
        for (int q = 0; q < 8; q++) {
            unsigned bf[2][2];
            const __half* pB = &SB[warp][el][q * 16 + hi * 8];
            unsigned addr = (unsigned)__cvta_generic_to_shared(pB);
            asm volatile("ldmatrix.sync.aligned.m8n8.x4.trans.shared.b16 {%0,%1,%2,%3}, [%4];"
                : "=r"(bf[0][0]), "=r"(bf[0][1]), "=r"(bf[1][0]), "=r"(bf[1][1])
                : "r"(addr));
            #pragma unroll
            for (int h = 0; h < 2; h++) {
                asm volatile(
                    "mma.sync.aligned.m16n8k16.row.col.f32.f16.f16.f32 "
                    "{%0,%1,%2,%3}, {%4,%5,%6,%7}, {%8,%9}, {%0,%1,%2,%3};"
                    : "+f"(acc[q*2+h][0]), "+f"(acc[q*2+h][1]),
                      "+f"(acc[q*2+h][2]), "+f"(acc[q*2+h][3])
                    : "r"(af[0]), "r"(af[1]), "r"(af[2]), "r"(af[3]),
                      "r"(bf[h][0]), "r"(bf[h][1]));
            }
        }
        __syncwarp();
    }

    const int g4 = lane >> 2, t4 = lane & 3;
    __half* Ap = g_A + (size_t)n * KT1;
    #pragma unroll
    for (int nt = 0; nt < 16; nt++) {
        *(__half2*)&Ap[(size_t)g4 * DIM + nt*8 + 2*t4] =
            __floats2half2_rn(acc[nt][0], acc[nt][1]);
        *(__half2*)&Ap[(size_t)(g4 + 8) * DIM + nt*8 + 2*t4] =
            __floats2half2_rn(acc[nt][2], acc[nt][3]);
    }
}

__global__ __launch_bounds__(256) void k_edgeT0() {
    __shared__ __half SA[8][16][24];
    __shared__ __half SB[8][16][24];

    const int warp = threadIdx.x >> 5;
    const int lane = threadIdx.x & 31;
    const int n = blockIdx.x * 8 + warp;
    if (n >= N_NODES) return;
    const int p0 = g_offS[n], p1 = g_offS[n + 1];

    float acc[2][4];
    #pragma unroll
    for (int nt = 0; nt < 2; nt++)
        #pragma unroll
        for (int i = 0; i < 4; i++) acc[nt][i] = 0.0f;

    const int el = lane & 15, hi = lane >> 4;
    const float rsigma = 15.0f / 0.8f;

    for (int c = p0; c < p1; c += 16) {
        const int p = c + el;
        const bool v = (p < p1);
        const int dst   = v ? g_dstS[p]  : 0;
        const float di  = v ? g_distS[p] : 1.0f;
        const float sw  = v ? g_swS[p]   : 0.0f;
        const float rinv = 1.0f / di;

        {
            const float v0 = (rinv - 0.2f) * rsigma - (float)(hi * 8);
            float sv = __expf(-0.5f * v0 * v0) * sw;
            const float Bp = __expf(v0);
            SA[warp][hi * 8 + 0][el] = __float2half(sv);
            sv *= Bp * EK0; SA[warp][hi * 8 + 1][el] = __float2half(sv);
            sv *= Bp * EK1; SA[warp][hi * 8 + 2][el] = __float2half(sv);
            sv *= Bp * EK2; SA[warp][hi * 8 + 3][el] = __float2half(sv);
            sv *= Bp * EK3; SA[warp][hi * 8 + 4][el] = __float2half(sv);
            sv *= Bp * EK4; SA[warp][hi * 8 + 5][el] = __float2half(sv);
            sv *= Bp * EK5; SA[warp][hi * 8 + 6][el] = __float2half(sv);
            sv *= Bp * EK6; SA[warp][hi * 8 + 7][el] = __float2half(sv);
        }
        {
            const int row = lane >> 1;
            const int rdst = __shfl_sync(0xffffffffu, dst, row);
            *(uint4*)&SB[warp][row][(lane & 1) * 8] =
                *(const uint4*)&g_z16h[rdst * 32 + (lane & 1) * 8];
        }
        __syncwarp();

        unsigned af[4];
        {
            const __half* pA = &SA[warp][el][hi * 8];
            unsigned addr = (unsigned)__cvta_generic_to_shared(pA);
            asm volatile("ldmatrix.sync.aligned.m8n8.x4.shared.b16 {%0,%1,%2,%3}, [%4];"
                : "=r"(af[0]), "=r"(af[1]), "=r"(af[2]), "=r"(af[3]) : "r"(addr));
        }
        unsigned bf[2][2];
        {
            const __half* pB = &SB[warp][el][hi * 8];
            unsigned addr = (unsigned)__cvta_generic_to_shared(pB);
            asm volatile("ldmatrix.sync.aligned.m8n8.x4.trans.shared.b16 {%0,%1,%2,%3}, [%4];"
                : "=r"(bf[0][0]), "=r"(bf[0][1]), "=r"(bf[1][0]), "=r"(bf[1][1])
                : "r"(addr));
        }
        #pragma unroll
        for (int h = 0; h < 2; h++) {
            asm volatile(
                "mma.sync.aligned.m16n8k16.row.col.f32.f16.f16.f32 "
                "{%0,%1,%2,%3}, {%4,%5,%6,%7}, {%8,%9}, {%0,%1,%2,%3};"
                : "+f"(acc[h][0]), "+f"(acc[h][1]), "+f"(acc[h][2]), "+f"(acc[h][3])
                : "r"(af[0]), "r"(af[1]), "r"(af[2]), "r"(af[3]),
                  "r"(bf[h][0]), "r"(bf[h][1]));
        }
        __syncwarp();
    }

    const int g4 = lane >> 2, t4 = lane & 3;
    __half* Ap = g_A + (size_t)n * KT0;
    #pragma unroll
    for (int nt = 0; nt < 2; nt++) {
        *(__half2*)&Ap[g4 * ZD + nt*8 + 2*t4] =
            __floats2half2_rn(acc[nt][0], acc[nt][1]);
        *(__half2*)&Ap[(g4 + 8) * ZD + nt*8 + 2*t4] =
            __floats2half2_rn(acc[nt][2], acc[nt][3]);
    }
}

// ---------------- fused node pipeline -------------------------------------
#define CPA16(dst, src, bytes) \
    asm volatile("cp.async.cg.shared.global [%0], [%1], 16, %2;" \
                 :: "r"(dst), "l"(src), "r"(bytes))

template<int LAYER>
__global__ __launch_bounds__(256) void k_nodeP(
    const __half* __restrict__ A, const __half* __restrict__ B,
    const __half* __restrict__ A2, const __half* __restrict__ W2,
    const float* __restrict__ bs,
    const __half* __restrict__ WaBase, const float* __restrict__ baBase,
    const __half* __restrict__ WbBase, const float* __restrict__ bbBase,
    __half* __restrict__ zih_out, float* __restrict__ out,
    int K, int K2)
{
    extern __shared__ char sm[];
    __half (*As)[136] = (__half(*)[136])sm;                       // 64x136
    __half (*Ws)[136] = (__half(*)[136])(sm + 17408);             // 128x136
    float  (*R)[DIM]  = (float (*)[DIM])(sm + 52224);             // 64x128 fp32
    __half (*Ag)[64][40]  = (__half(*)[64][40]) (sm + 17408);
    __half (*Bg)[32][136] = (__half(*)[32][136])(sm + 17408 + 10240);

    const int t = threadIdx.x;
    const int warp = t >> 5, lane = t & 31;
    const int wm = (warp & 1) * 32, wn = (warp >> 1) * 32;
    const int m0 = blockIdx.x * 64;
    const int g4 = lane >> 2, t4 = lane & 3;

    const int arow = t >> 2, ak = (t & 3) * 8;
    const int brow = t >> 4, bcol = (t & 15) * 8;
    const int gm = m0 + arow;
    const int apred = (gm < N_NODES) ? 16 : 0;
    const __half* Abase = &A[(size_t)gm * K];

    float acc[2][4][4];
    #pragma unroll
    for (int mt = 0; mt < 2; mt++)
        #pragma unroll
        for (int nt = 0; nt < 4; nt++)
            #pragma unroll
            for (int i = 0; i < 4; i++) acc[mt][nt][i] = 0.0f;

    const int T = K >> 5;

    {
        unsigned da = (unsigned)__cvta_generic_to_shared(&Ag[0][arow][ak]);
        CPA16(da, Abase + ak, apred);
        unsigned db0 = (unsigned)__cvta_generic_to_shared(&Bg[0][brow][bcol]);
        unsigned db1 = (unsigned)__cvta_generic_to_shared(&Bg[0][16 + brow][bcol]);
        CPA16(db0, &B[(size_t)brow * DIM + bcol], 16);
        CPA16(db1, &B[(size_t)(16 + brow) * DIM + bcol], 16);
        asm volatile("cp.async.commit_group;");
    }

    for (int tt = 0; tt < T; tt++) {
        if (tt + 1 < T) {
            const int buf = (tt + 1) & 1, k0 = (tt + 1) * 32;
            unsigned da = (unsigned)__cvta_generic_to_shared(&Ag[buf][arow][ak]);
            CPA16(da, Abase + k0 + ak, apred);
            unsigned db0 = (unsigned)__cvta_generic_to_shared(&Bg[buf][brow][bcol]);
            unsigned db1 = (unsigned)__cvta_generic_to_shared(&Bg[buf][16 + brow][bcol]);
            CPA16(db0, &B[(size_t)(k0 + brow) * DIM + bcol], 16);
            CPA16(db1, &B[(size_t)(k0 + 16 + brow) * DIM + bcol], 16);
            asm volatile("cp.async.commit_group;");
            asm volatile("cp.async.wait_group 1;");
        } else {
            asm volatile("cp.async.wait_group 0;");
        }
        __syncthreads();

        const int buf = tt & 1;
        #pragma unroll
        for (int sub = 0; sub < 2; sub++) {
            const int kc = sub * 16;
            unsigned af[2][4];
            #pragma unroll
            for (int mt = 0; mt < 2; mt++) {
                const __half* p = &Ag[buf][wm + mt*16 + (lane & 15)][kc + ((lane >> 4) << 3)];
                unsigned addr = (unsigned)__cvta_generic_to_shared(p);
                asm volatile("ldmatrix.sync.aligned.m8n8.x4.shared.b16 {%0,%1,%2,%3}, [%4];"
                    : "=r"(af[mt][0]), "=r"(af[mt][1]), "=r"(af[mt][2]), "=r"(af[mt][3])
                    : "r"(addr));
            }
            unsigned bf[4][2];
            #pragma unroll
            for (int q = 0; q < 2; q++) {
                const __half* p = &Bg[buf][kc + (lane & 15)][wn + q*16 + ((lane >> 4) << 3)];
                unsigned addr = (unsigned)__cvta_generic_to_shared(p);
                asm volatile("ldmatrix.sync.aligned.m8n8.x4.trans.shared.b16 {%0,%1,%2,%3}, [%4];"
                    : "=r"(bf[q*2][0]), "=r"(bf[q*2][1]), "=r"(bf[q*2+1][0]), "=r"(bf[q*2+1][1])
                    : "r"(addr));
            }
            #pragma unroll
            for (int mt = 0; mt < 2; mt++)
                #pragma unroll
                for (int nt = 0; nt < 4; nt++) {
                    asm volatile(
                        "mma.sync.aligned.m16n8k16.row.col.f32.f16.f16.f32 "
                        "{%0,%1,%2,%3}, {%4,%5,%6,%7}, {%8,%9}, {%0,%1,%2,%3};"
                        : "+f"(acc[mt][nt][0]), "+f"(acc[mt][nt][1]),
                          "+f"(acc[mt][nt][2]), "+f"(acc[mt][nt][3])
                        : "r"(af[mt][0]), "r"(af[mt][1]), "r"(af[mt][2]), "r"(af[mt][3]),
                          "r"(bf[nt][0]), "r"(bf[nt][1]));
                }
        }
        __syncthreads();
    }

    // ---- second GEMM: z @ Ws ----
    const int T2 = K2 >> 5;
    for (int q = 0; q < T2; q++) {
        uint4 a0 = make_uint4(0,0,0,0);
        if (gm < N_NODES)
            a0 = *(const uint4*)&A2[(size_t)gm * K2 + q*32 + ak];
        uint4 b0 = *(const uint4*)&W2[(size_t)(q*32 + brow) * DIM + bcol];
        uint4 b1 = *(const uint4*)&W2[(size_t)(q*32 + 16 + brow) * DIM + bcol];
        __syncthreads();
        *(uint4*)&Ag[0][arow][ak] = a0;
        *(uint4*)&Bg[0][brow][bcol]      = b0;
        *(uint4*)&Bg[0][16 + brow][bcol] = b1;
        __syncthreads();

        #pragma unroll
        for (int sub = 0; sub < 2; sub++) {
            const int kc = sub * 16;
            unsigned af[2][4];
            #pragma unroll
            for (int mt = 0; mt < 2; mt++) {
                const __half* p = &Ag[0][wm + mt*16 + (lane & 15)][kc + ((lane >> 4) << 3)];
                unsigned addr = (unsigned)__cvta_generic_to_shared(p);
                asm volatile("ldmatrix.sync.aligned.m8n8.x4.shared.b16 {%0,%1,%2,%3}, [%4];"
                    : "=r"(af[mt][0]), "=r"(af[mt][1]), "=r"(af[mt][2]), "=r"(af[mt][3])
                    : "r"(addr));
            }
            unsigned bf[4][2];
            #pragma unroll
            for (int qq = 0; qq < 2; qq++) {
                const __half* p = &Bg[0][kc + (lane & 15)][wn + qq*16 + ((lane >> 4) << 3)];
                unsigned addr = (unsigned)__cvta_generic_to_shared(p);
                asm volatile("ldmatrix.sync.aligned.m8n8.x4.trans.shared.b16 {%0,%1,%2,%3}, [%4];"
                    : "=r"(bf[qq*2][0]), "=r"(bf[qq*2][1]), "=r"(bf[qq*2+1][0]), "=r"(bf[qq*2+1][1])
                    : "r"(addr));
            }
            #pragma unroll
            for (int mt = 0; mt < 2; mt++)
                #pragma unroll
                for (int nt = 0; nt < 4; nt++) {
                    asm volatile(
                        "mma.sync.aligned.m16n8k16.row.col.f32.f16.f16.f32 "
                        "{%0,%1,%2,%3}, {%4,%5,%6,%7}, {%8,%9}, {%0,%1,%2,%3};"
                        : "+f"(acc[mt][nt][0]), "+f"(acc[mt][nt][1]),
                          "+f"(acc[mt][nt][2]), "+f"(acc[mt][nt][3])
                        : "r"(af[mt][0]), "r"(af[mt][1]), "r"(af[mt][2]), "r"(af[mt][3]),
                          "r"(bf[nt][0]), "r"(bf[nt][1]));
                }
        }
        __syncthreads();
    }

    // ---- epilogue 1: zi-tile = silu(acc + bs) -> R (fp32) + As (fp16) ----
    #pragma unroll
    for (int mt = 0; mt < 2; mt++) {
        #pragma unroll
        for (int nt = 0; nt < 4; nt++) {
            int col = wn + nt*8 + 2*t4;
            float b0 = bs[col], b1 = bs[col + 1];
            #pragma unroll
            for (int h = 0; h < 2; h++) {
                int rl = wm + mt*16 + g4 + h*8;
                float ox = silu_f(acc[mt][nt][h*2 + 0] + b0);
                float oy = silu_f(acc[mt][nt][h*2 + 1] + b1);
                R[rl][col] = ox; R[rl][col + 1] = oy;
                *(__half2*)&As[rl][col] = __floats2half2_rn(ox, oy);
            }
        }
    }
    __syncthreads();

    // ---- phase 2: 3x onsite blocks ----
    const int rw = t >> 1, cw = (t & 1) * 64;
    for (int j = 0; j < 3; j++) {
        const __half* Wa = WaBase + j * DIM * DIM;
        const __half* Wb = WbBase + j * DIM * DIM;
        const float*  ba = baBase + j * DIM;
        const float*  bb = bbBase + j * DIM;

        #pragma unroll
        for (int i = 0; i < 8; i++)
            *(uint4*)&Ws[rw][cw + i*8] = *(const uint4*)&Wa[rw * DIM + cw + i*8];
        __syncthreads();

        #pragma unroll
        for (int mt = 0; mt < 2; mt++)
            #pragma unroll
            for (int nt = 0; nt < 4; nt++)
                #pragma unroll
                for (int i = 0; i < 4; i++) acc[mt][nt][i] = 0.0f;

        #pragma unroll
        for (int kc = 0; kc < 128; kc += 16) {
            unsigned af[2][4];
            #pragma unroll
            for (int mt = 0; mt < 2; mt++) {
                const __half* p = &As[wm + mt*16 + (lane & 15)][kc + ((lane >> 4) << 3)];
                unsigned addr = (unsigned)__cvta_generic_to_shared(p);
                asm volatile("ldmatrix.sync.aligned.m8n8.x4.shared.b16 {%0,%1,%2,%3}, [%4];"
                    : "=r"(af[mt][0]), "=r"(af[mt][1]), "=r"(af[mt][2]), "=r"(af[mt][3])
                    : "r"(addr));
            }
            unsigned bf[4][2];
            #pragma unroll
            for (int q = 0; q < 2; q++) {
                const __half* p = &Ws[kc + (lane & 15)][wn + q*16 + ((lane >> 4) << 3)];
                unsigned addr = (unsigned)__cvta_generic_to_shared(p);
                asm volatile("ldmatrix.sync.aligned.m8n8.x4.trans.shared.b16 {%0,%1,%2,%3}, [%4];"
                    : "=r"(bf[q*2][0]), "=r"(bf[q*2][1]), "=r"(bf[q*2+1][0]), "=r"(bf[q*2+1][1])
                    : "r"(addr));
            }
            #pragma unroll
            for (int mt = 0; mt < 2; mt++)
                #pragma unroll
                for (int nt = 0; nt < 4; nt++) {
                    asm volatile(
                        "mma.sync.aligned.m16n8k16.row.col.f32.f16.f16.f32 "
                        "{%0,%1,%2,%3}, {%4,%5,%6,%7}, {%8,%9}, {%0,%1,%2,%3};"
                        : "+f"(acc[mt][nt][0]), "+f"(acc[mt][nt][1]),
                          "+f"(acc[mt][nt][2]), "+f"(acc[mt][nt][3])
                        : "r"(af[mt][0]), "r"(af[mt][1]), "r"(af[mt][2]), "r"(af[mt][3]),
                          "r"(bf[nt][0]), "r"(bf[nt][1]));
                }
        }
        __syncthreads();

        #pragma unroll
        for (int mt = 0; mt < 2; mt++) {
            #pragma unroll
            for (int nt = 0; nt < 4; nt++) {
                int col = wn + nt*8 + 2*t4;
                float b0 = ba[col], b1 = ba[col + 1];
                int r0 = wm + mt*16 + g4;
                *(__half2*)&As[r0][col] =
                    __floats2half2_rn(silu_f(acc[mt][nt][0] + b0), silu_f(acc[mt][nt][1] + b1));
                *(__half2*)&As[r0 + 8][col] =
                    __floats2half2_rn(silu_f(acc[mt][nt][2] + b0), silu_f(acc[mt][nt][3] + b1));
            }
        }
        #pragma unroll
        for (int i = 0; i < 8; i++)
            *(uint4*)&Ws[rw][cw + i*8] = *(const uint4*)&Wb[rw * DIM + cw + i*8];
        __syncthreads();

        #pragma unroll
        for (int mt = 0; mt < 2; mt++)
            #pragma unroll
            for (int nt = 0; nt < 4; nt++)
                #pragma unroll
                for (int i = 0; i < 4; i++) acc[mt][nt][i] = 0.0f;

        #pragma unroll
        for (int kc = 0; kc < 128; kc += 16) {
            unsigned af[2][4];
            #pragma unroll
            for (int mt = 0; mt < 2; mt++) {
                const __half* p = &As[wm + mt*16 + (lane & 15)][kc + ((lane >> 4) << 3)];
                unsigned addr = (unsigned)__cvta_generic_to_shared(p);
                asm volatile("ldmatrix.sync.aligned.m8n8.x4.shared.b16 {%0,%1,%2,%3}, [%4];"
                    : "=r"(af[mt][0]), "=r"(af[mt][1]), "=r"(af[mt][2]), "=r"(af[mt][3])
                    : "r"(addr));
            }
            unsigned bf[4][2];
            #pragma unroll
            for (int q = 0; q < 2; q++) {
                const __half* p = &Ws[kc + (lane & 15)][wn + q*16 + ((lane >> 4) << 3)];
                unsigned addr = (unsigned)__cvta_generic_to_shared(p);
                asm volatile("ldmatrix.sync.aligned.m8n8.x4.trans.shared.b16 {%0,%1,%2,%3}, [%4];"
                    : "=r"(bf[q*2][0]), "=r"(bf[q*2][1]), "=r"(bf[q*2+1][0]), "=r"(bf[q*2+1][1])
                    : "r"(addr));
            }
            #pragma unroll
            for (int mt = 0; mt < 2; mt++)
                #pragma unroll
                for (int nt = 0; nt < 4; nt++) {
                    asm volatile(
                        "mma.sync.aligned.m16n8k16.row.col.f32.f16.f16.f32 "
                        "{%0,%1,%2,%3}, {%4,%5,%6,%7}, {%8,%9}, {%0,%1,%2,%3};"
                        : "+f"(acc[mt][nt][0]), "+f"(acc[mt][nt][1]),
                          "+f"(acc[mt][nt][2]), "+f"(acc[mt][nt][3])
                        : "r"(af[mt][0]), "r"(af[mt][1]), "r"(af[mt][2]), "r"(af[mt][3]),
                          "r"(bf[nt][0]), "r"(bf[nt][1]));
                }
        }
        __syncthreads();

        #pragma unroll
        for (int mt = 0; mt < 2; mt++) {
            #pragma unroll
            for (int nt = 0; nt < 4; nt++) {
                int col = wn + nt*8 + 2*t4;
                float b0 = bb[col], b1 = bb[col + 1];
                #pragma unroll
                for (int h = 0; h < 2; h++) {
                    int rl = wm + mt*16 + g4 + h*8;
                    float2 o;
                    o.x = acc[mt][nt][h*2 + 0] + b0 + R[rl][col];
                    o.y = acc[mt][nt][h*2 + 1] + b1 + R[rl][col + 1];
                    if (j < 2) {
                        R[rl][col] = o.x; R[rl][col + 1] = o.y;
                        *(__half2*)&As[rl][col] = __floats2half2_rn(o.x, o.y);
                    } else {
                        int row = m0 + rl;
                        if (row < N_NODES) {
                            if (LAYER == 0) {
                                *(__half2*)&zih_out[(size_t)row * DIM + col] =
                                    __floats2half2_rn(o.x, o.y);
                                *(float2*)&out[(size_t)N_NODES * DIM + (size_t)row * 2 * DIM + col] = o;
                            } else {
                                *(float2*)&out[(size_t)row * DIM + col] = o;
                                *(float2*)&out[(size_t)N_NODES * DIM + (size_t)row * 2 * DIM + DIM + col] = o;
                            }
                        }
                    }
                }
            }
        }
        __syncthreads();
    }
}

// ---------------- host driver ----------------
extern "C" void kernel_launch(void* const* d_in, const int* in_sizes, int n_in,
                              void* d_out, int out_size)
{
    const int*   species = (const int*)  d_in[0];
    const int*   esrc    = (const int*)  d_in[1];
    const int*   edst    = (const int*)  d_in[2];
    const float* dist    = (const float*)d_in[3];
    const float* swp     = (const float*)d_in[4];
    const float* Z       = (const float*)d_in[5];
    const float* Ws0     = (const float*)d_in[6];
    const float* bs0     = (const float*)d_in[7];
    const float* V0      = (const float*)d_in[8];
    const float* Ws1     = (const float*)d_in[9];
    const float* bs1     = (const float*)d_in[10];
    const float* V1      = (const float*)d_in[11];
    const float* Won_a   = (const float*)d_in[12];
    const float* bon_a   = (const float*)d_in[13];
    const float* Won_b   = (const float*)d_in[14];
    const float* bon_b   = (const float*)d_in[15];
    float* out = (float*)d_out;

    __half *Ah, *Vh0, *Vh1, *z16h, *zih, *Ws0h, *Ws1h, *Wah, *Wbh;
    cudaGetSymbolAddress((void**)&Ah,    g_A);
    cudaGetSymbolAddress((void**)&Vh0,   g_Vh0);
    cudaGetSymbolAddress((void**)&Vh1,   g_Vh1);
    cudaGetSymbolAddress((void**)&z16h,  g_z16h);
    cudaGetSymbolAddress((void**)&zih,   g_zih);
    cudaGetSymbolAddress((void**)&Ws0h,  g_Ws0h);
    cudaGetSymbolAddress((void**)&Ws1h,  g_Ws1h);
    cudaGetSymbolAddress((void**)&Wah,   g_Wah);
    cudaGetSymbolAddress((void**)&Wbh,   g_Wbh);

    const int MB64 = (N_NODES + 63) / 64;       // 313
    const int EB = (N_EDGES + 255) / 256;
    const int NBK = (N_NODES + 7) / 8;
    const int PREP_N = N_NODES * 32;            // 640000 >= N_EDGES

    const int NODE_SMEM = 17408 + 34816 + 64 * DIM * 4;   // 84992
    static int attr_done = 0;
    if (!attr_done) {
        cudaFuncSetAttribute(k_nodeP<0>, cudaFuncAttributeMaxDynamicSharedMemorySize, NODE_SMEM);
        cudaFuncSetAttribute(k_nodeP<1>, cudaFuncAttributeMaxDynamicSharedMemorySize, NODE_SMEM);
        attr_done = 1;
    }

    // ---- preprocessing ----
    k_prep<<<(PREP_N + 255) / 256, 256>>>(species, Z, V0, V1, Ws0, Ws1, Won_a, Won_b, esrc);
    k_scan1<<<SCAN_BLKS, 256>>>();
    k_scan2<<<1, 128>>>();
    k_scan3<<<SCAN_BLKS, 256>>>();
    k_fillS<<<EB, 256>>>(esrc, edst, dist, swp);

    // ---- layer 0 ----
    k_edgeT0<<<NBK, 256>>>();
    k_nodeP<0><<<MB64, 256, NODE_SMEM>>>(Ah, Vh0, z16h, Ws0h, bs0,
        Wah + 0*3*DIM*DIM, bon_a + 0*3*DIM, Wbh + 0*3*DIM*DIM, bon_b + 0*3*DIM,
        zih, out, KT0, 32);

    // ---- layer 1 ----
    k_edgeT1<<<NBK, 256>>>();
    k_nodeP<1><<<MB64, 256, NODE_SMEM>>>(Ah, Vh1, zih, Ws1h, bs1,
        Wah + 1*3*DIM*DIM, bon_a + 1*3*DIM, Wbh + 1*3*DIM*DIM, bon_b + 1*3*DIM,
        zih, out, KT1, DIM);
}

// round 16
// speedup vs baseline: 1.1093x; 1.0031x over previous
#include <cuda_runtime.h>
#include <cuda_fp16.h>
#include <math.h>

#define N_NODES 20000
#define N_EDGES 400000
#define DIM 128
#define NB 16
#define ZD 16
#define NLAYERS 2
#define KT1 (NB*DIM)   // 2048
#define KT0 (NB*ZD)    // 256
#define SCAN_BLKS ((N_NODES + 255) / 256)   // 79

// ---------------- device scratch (static, no allocations) ----------------
__device__ __half g_A[(size_t)N_NODES*KT1];     // aggregated T rows (fp16)
__device__ __half g_z16h[N_NODES*32];           // layer0 features, padded K2=32
__device__ __half g_zih[N_NODES*DIM];           // fp16 layer0 output
__device__ __half g_Vh0[KT0*DIM];               // V0.reshape(-1,128) fp16
__device__ __half g_Vh1[KT1*DIM];               // V1.reshape(-1,128) fp16
__device__ __half g_Ws0h[32*DIM];               // Ws0 padded to 32 rows, fp16
__device__ __half g_Ws1h[DIM*DIM];              // Ws1 fp16
__device__ __half g_Wah[NLAYERS*3*DIM*DIM];     // onsite Wa fp16
__device__ __half g_Wbh[NLAYERS*3*DIM*DIM];     // onsite Wb fp16

// CSR by src. g_degS starts zero (module load); k_scan3 re-zeroes each run.
__device__ int   g_degS[N_NODES], g_offS[N_NODES+1], g_curS[N_NODES];
__device__ int   g_part[128];
__device__ int   g_dstS[N_EDGES];
__device__ float g_distS[N_EDGES];
__device__ float g_swS[N_EDGES];

__device__ __forceinline__ float silu_f(float x) {
    return x / (1.0f + __expf(-x));
}

// exp(-(k+0.5)) for k = 0..6
#define EK0 0.60653066f
#define EK1 0.22313016f
#define EK2 0.082084998f
#define EK3 0.030197383f
#define EK4 0.011108997f
#define EK5 0.0040867714f
#define EK6 0.0015034391f

// ---------------- merged preprocessing (+ degree count) -------------------
__global__ void k_prep(const int* __restrict__ species, const float* __restrict__ Z,
                       const float* __restrict__ V0, const float* __restrict__ V1,
                       const float* __restrict__ Ws0, const float* __restrict__ Ws1,
                       const float* __restrict__ Wa, const float* __restrict__ Wb,
                       const int* __restrict__ esrc)
{
    int t = blockIdx.x * blockDim.x + threadIdx.x;
    if (t < N_NODES * 32) {
        int n = t >> 5, c = t & 31;
        g_z16h[t] = __float2half(c < ZD ? Z[species[n] * ZD + c] : 0.0f);
    }
    if (t < KT1 * DIM) g_Vh1[t] = __float2half(V1[t]);
    if (t < KT0 * DIM) g_Vh0[t] = __float2half(V0[t]);
    if (t < NLAYERS * 3 * DIM * DIM) {
        g_Wah[t] = __float2half(Wa[t]);
        g_Wbh[t] = __float2half(Wb[t]);
    }
    if (t < 32 * DIM) {
        int r = t >> 7;
        g_Ws0h[t] = __float2half(r < ZD ? Ws0[t] : 0.0f);
    }
    if (t < DIM * DIM) g_Ws1h[t] = __float2half(Ws1[t]);
    if (t < N_EDGES) atomicAdd(&g_degS[esrc[t]], 1);   // degS zero on entry
}

// ---------------- parallel scan ----------------
__global__ void k_scan1() {
    __shared__ int s[256];
    int t = threadIdx.x, idx = blockIdx.x * 256 + t;
    s[t] = (idx < N_NODES) ? g_degS[idx] : 0;
    __syncthreads();
    #pragma unroll
    for (int d = 128; d > 0; d >>= 1) {
        if (t < d) s[t] += s[t + d];
        __syncthreads();
    }
    if (t == 0) g_part[blockIdx.x] = s[0];
}
__global__ void k_scan2() {
    __shared__ int s[128];
    int t = threadIdx.x;
    int v = (t < SCAN_BLKS) ? g_part[t] : 0;
    s[t] = v;
    __syncthreads();
    #pragma unroll
    for (int d = 1; d < 128; d <<= 1) {
        int x = (t >= d) ? s[t - d] : 0;
        __syncthreads();
        s[t] += x;
        __syncthreads();
    }
    if (t < SCAN_BLKS) g_part[t] = s[t] - v;
    if (t == 127) g_offS[N_NODES] = s[127];
}
__global__ void k_scan3() {
    __shared__ int s[256];
    int t = threadIdx.x, idx = blockIdx.x * 256 + t;
    int v = (idx < N_NODES) ? g_degS[idx] : 0;
    s[t] = v;
    __syncthreads();
    #pragma unroll
    for (int d = 1; d < 256; d <<= 1) {
        int x = (t >= d) ? s[t - d] : 0;
        __syncthreads();
        s[t] += x;
        __syncthreads();
    }
    int excl = s[t] - v + g_part[blockIdx.x];
    if (idx < N_NODES) {
        g_offS[idx] = excl;
        g_curS[idx] = excl;
        g_degS[idx] = 0;        // self-clean for next replay
    }
}
__global__ void k_fillS(const int* __restrict__ esrc, const int* __restrict__ edst,
                        const float* __restrict__ dist, const float* __restrict__ sw) {
    int e = blockIdx.x * blockDim.x + threadIdx.x;
    if (e < N_EDGES) {
        int pos = atomicAdd(&g_curS[esrc[e]], 1);
        g_dstS[pos]  = edst[e];
        g_distS[pos] = dist[e];
        g_swS[pos]   = sw[e];
    }
}

// ---------------- edge aggregation via tensor cores -----------------------
// Layer 1: 2-chunk ILP — 32 edges per iteration, both chunks' LDGs in flight.
__global__ __launch_bounds__(256) void k_edgeT1() {
    extern __shared__ char esm[];
    __half (*SA)[2][16][24]  = (__half(*)[2][16][24])esm;               // 12288 B
    __half (*SB)[2][16][136] = (__half(*)[2][16][136])(esm + 12288);    // 69632 B

    const int warp = threadIdx.x >> 5;
    const int lane = threadIdx.x & 31;
    const int n = blockIdx.x * 8 + warp;
    if (n >= N_NODES) return;
    const int p0 = g_offS[n], p1 = g_offS[n + 1];

    float acc[16][4];
    #pragma unroll
    for (int nt = 0; nt < 16; nt++)
        #pragma unroll
        for (int i = 0; i < 4; i++) acc[nt][i] = 0.0f;

    const int el = lane & 15, hi = lane >> 4;
    const float rsigma = 15.0f / 0.8f;

    for (int c = p0; c < p1; c += 32) {
        const int nch = (c + 16 < p1) ? 2 : 1;
        int dstu[2];
        #pragma unroll
        for (int u = 0; u < 2; u++) {
            if (u >= nch) { dstu[u] = 0; continue; }
            const int p = c + u * 16 + el;
            const bool v = (p < p1);
            dstu[u] = v ? g_dstS[p] : 0;
            const float di = v ? g_distS[p] : 1.0f;
            const float sw = v ? g_swS[p]   : 0.0f;
            const float rinv = 1.0f / di;
            const float v0 = (rinv - 0.2f) * rsigma - (float)(hi * 8);
            float sv = __expf(-0.5f * v0 * v0) * sw;
            const float Bp = __expf(v0);
            SA[warp][u][hi*8+0][el] = __float2half(sv);
            sv *= Bp * EK0; SA[warp][u][hi*8+1][el] = __float2half(sv);
            sv *= Bp * EK1; SA[warp][u][hi*8+2][el] = __float2half(sv);
            sv *= Bp * EK2; SA[warp][u][hi*8+3][el] = __float2half(sv);
            sv *= Bp * EK3; SA[warp][u][hi*8+4][el] = __float2half(sv);
            sv *= Bp * EK4; SA[warp][u][hi*8+5][el] = __float2half(sv);
            sv *= Bp * EK5; SA[warp][u][hi*8+6][el] = __float2half(sv);
            sv *= Bp * EK6; SA[warp][u][hi*8+7][el] = __float2half(sv);
        }
        #pragma unroll
        for (int u = 0; u < 2; u++) {
            if (u >= nch) continue;
            #pragma unroll
            for (int r2 = 0; r2 < 8; r2++) {
                const int row = r2 * 2 + hi;
                const int rdst = __shfl_sync(0xffffffffu, dstu[u], row);
                *(uint4*)&SB[warp][u][row][el * 8] =
                    *(const uint4*)&g_zih[(size_t)rdst * DIM + el * 8];
            }
        }
        __syncwarp();

        #pragma unroll
        for (int u = 0; u < 2; u++) {
            if (u >= nch) continue;
            unsigned af[4];
            {
                const __half* pA = &SA[warp][u][el][hi * 8];
                unsigned addr = (unsigned)__cvta_generic_to_shared(pA);
                asm volatile("ldmatrix.sync.aligned.m8n8.x4.shared.b16 {%0,%1,%2,%3}, [%4];"
                    : "=r"(af[0]), "=r"(af[1]), "=r"(af[2]), "=r"(af[3]) : "r"(addr));
            }
            #pragma unroll
            for (int q = 0; q < 8; q++) {
                unsigned bf[2][2];
                const __half* pB = &SB[warp][u][el][q * 16 + hi * 8];
                unsigned addr = (unsigned)__cvta_generic_to_shared(pB);
                asm volatile("ldmatrix.sync.aligned.m8n8.x4.trans.shared.b16 {%0,%1,%2,%3}, [%4];"
                    : "=r"(bf[0][0]), "=r"(bf[0][1]), "=r"(bf[1][0]), "=r"(bf[1][1])
                    : "r"(addr));
                #pragma unroll
                for (int h = 0; h < 2; h++) {
                    asm volatile(
                        "mma.sync.aligned.m16n8k16.row.col.f32.f16.f16.f32 "
                        "{%0,%1,%2,%3}, {%4,%5,%6,%7}, {%8,%9}, {%0,%1,%2,%3};"
                        : "+f"(acc[q*2+h][0]), "+f"(acc[q*2+h][1]),
                          "+f"(acc[q*2+h][2]), "+f"(acc[q*2+h][3])
                        : "r"(af[0]), "r"(af[1]), "r"(af[2]), "r"(af[3]),
                          "r"(bf[h][0]), "r"(bf[h][1]));
                }
            }
        }
        __syncwarp();
    }

    const int g4 = lane >> 2, t4 = lane & 3;
    __half* Ap = g_A + (size_t)n * KT1;
    #pragma unroll
    for (int nt = 0; nt < 16; nt++) {
        *(__half2*)&Ap[(size_t)g4 * DIM + nt*8 + 2*t4] =
            __floats2half2_rn(acc[nt][0], acc[nt][1]);
        *(__half2*)&Ap[(size_t)(g4 + 8) * DIM + nt*8 + 2*t4] =
            __floats2half2_rn(acc[nt][2], acc[nt][3]);
    }
}

// Layer 0: same 2-chunk ILP, small z rows (static smem).
__global__ __launch_bounds__(256) void k_edgeT0() {
    __shared__ __half SA[8][2][16][24];
    __shared__ __half SB[8][2][16][24];

    const int warp = threadIdx.x >> 5;
    const int lane = threadIdx.x & 31;
    const int n = blockIdx.x * 8 + warp;
    if (n >= N_NODES) return;
    const int p0 = g_offS[n], p1 = g_offS[n + 1];

    float acc[2][4];
    #pragma unroll
    for (int nt = 0; nt < 2; nt++)
        #pragma unroll
        for (int i = 0; i < 4; i++) acc[nt][i] = 0.0f;

    const int el = lane & 15, hi = lane >> 4;
    const float rsigma = 15.0f / 0.8f;

    for (int c = p0; c < p1; c += 32) {
        const int nch = (c + 16 < p1) ? 2 : 1;
        int dstu[2];
        #pragma unroll
        for (int u = 0; u < 2; u++) {
            if (u >= nch) { dstu[u] = 0; continue; }
            const int p = c + u * 16 + el;
            const bool v = (p < p1);
            dstu[u] = v ? g_dstS[p] : 0;
            const float di = v ? g_distS[p] : 1.0f;
            const float sw = v ? g_swS[p]   : 0.0f;
            const float rinv = 1.0f / di;
            const float v0 = (rinv - 0.2f) * rsigma - (float)(hi * 8);
            float sv = __expf(-0.5f * v0 * v0) * sw;
            const float Bp = __expf(v0);
            SA[warp][u][hi*8+0][el] = __float2half(sv);
            sv *= Bp * EK0; SA[warp][u][hi*8+1][el] = __float2half(sv);
            sv *= Bp * EK1; SA[warp][u][hi*8+2][el] = __float2half(sv);
            sv *= Bp * EK2; SA[warp][u][hi*8+3][el] = __float2half(sv);
            sv *= Bp * EK3; SA[warp][u][hi*8+4][el] = __float2half(sv);
            sv *= Bp * EK4; SA[warp][u][hi*8+5][el] = __float2half(sv);
            sv *= Bp * EK5; SA[warp][u][hi*8+6][el] = __float2half(sv);
            sv *= Bp * EK6; SA[warp][u][hi*8+7][el] = __float2half(sv);
        }
        #pragma unroll
        for (int u = 0; u < 2; u++) {
            if (u >= nch) continue;
            const int row = lane >> 1;
            const int rdst = __shfl_sync(0xffffffffu, dstu[u], row);
            *(uint4*)&SB[warp][u][row][(lane & 1) * 8] =
                *(const uint4*)&g_z16h[rdst * 32 + (lane & 1) * 8];
        }
        __syncwarp();

        #pragma unroll
        for (int u = 0; u < 2; u++) {
            if (u >= nch) continue;
            unsigned af[4];
            {
                const __half* pA = &SA[warp][u][el][hi * 8];
                unsigned addr = (unsigned)__cvta_generic_to_shared(pA);
                asm volatile("ldmatrix.sync.aligned.m8n8.x4.shared.b16 {%0,%1,%2,%3}, [%4];"
                    : "=r"(af[0]), "=r"(af[1]), "=r"(af[2]), "=r"(af[3]) : "r"(addr));
            }
            unsigned bf[2][2];
            {
                const __half* pB = &SB[warp][u][el][hi * 8];
                unsigned addr = (unsigned)__cvta_generic_to_shared(pB);
                asm volatile("ldmatrix.sync.aligned.m8n8.x4.trans.shared.b16 {%0,%1,%2,%3}, [%4];"
                    : "=r"(bf[0][0]), "=r"(bf[0][1]), "=r"(bf[1][0]), "=r"(bf[1][1])
                    : "r"(addr));
            }
            #pragma unroll
            for (int h = 0; h < 2; h++) {
                asm volatile(
                    "mma.sync.aligned.m16n8k16.row.col.f32.f16.f16.f32 "
                    "{%0,%1,%2,%3}, {%4,%5,%6,%7}, {%8,%9}, {%0,%1,%2,%3};"
                    : "+f"(acc[h][0]), "+f"(acc[h][1]), "+f"(acc[h][2]), "+f"(acc[h][3])
                    : "r"(af[0]), "r"(af[1]), "r"(af[2]), "r"(af[3]),
                      "r"(bf[h][0]), "r"(bf[h][1]));
            }
        }
        __syncwarp();
    }

    const int g4 = lane >> 2, t4 = lane & 3;
    __half* Ap = g_A + (size_t)n * KT0;
    #pragma unroll
    for (int nt = 0; nt < 2; nt++) {
        *(__half2*)&Ap[g4 * ZD + nt*8 + 2*t4] =
            __floats2half2_rn(acc[nt][0], acc[nt][1]);
        *(__half2*)&Ap[(g4 + 8) * ZD + nt*8 + 2*t4] =
            __floats2half2_rn(acc[nt][2], acc[nt][3]);
    }
}

// ---------------- fused node pipeline -------------------------------------
#define CPA16(dst, src, bytes) \
    asm volatile("cp.async.cg.shared.global [%0], [%1], 16, %2;" \
                 :: "r"(dst), "l"(src), "r"(bytes))

template<int LAYER>
__global__ __launch_bounds__(256) void k_nodeP(
    const __half* __restrict__ A, const __half* __restrict__ B,
    const __half* __restrict__ A2, const __half* __restrict__ W2,
    const float* __restrict__ bs,
    const __half* __restrict__ WaBase, const float* __restrict__ baBase,
    const __half* __restrict__ WbBase, const float* __restrict__ bbBase,
    __half* __restrict__ zih_out, float* __restrict__ out,
    int K, int K2)
{
    extern __shared__ char sm[];
    __half (*As)[136] = (__half(*)[136])sm;                       // 64x136
    __half (*Ws)[136] = (__half(*)[136])(sm + 17408);             // 128x136
    float  (*R)[DIM]  = (float (*)[DIM])(sm + 52224);             // 64x128 fp32
    __half (*Ag)[64][40]  = (__half(*)[64][40]) (sm + 17408);
    __half (*Bg)[32][136] = (__half(*)[32][136])(sm + 17408 + 10240);

    const int t = threadIdx.x;
    const int warp = t >> 5, lane = t & 31;
    const int wm = (warp & 1) * 32, wn = (warp >> 1) * 32;
    const int m0 = blockIdx.x * 64;
    const int g4 = lane >> 2, t4 = lane & 3;

    const int arow = t >> 2, ak = (t & 3) * 8;
    const int brow = t >> 4, bcol = (t & 15) * 8;
    const int gm = m0 + arow;
    const int apred = (gm < N_NODES) ? 16 : 0;
    const __half* Abase = &A[(size_t)gm * K];

    float acc[2][4][4];
    #pragma unroll
    for (int mt = 0; mt < 2; mt++)
        #pragma unroll
        for (int nt = 0; nt < 4; nt++)
            #pragma unroll
            for (int i = 0; i < 4; i++) acc[mt][nt][i] = 0.0f;

    const int T = K >> 5;

    {
        unsigned da = (unsigned)__cvta_generic_to_shared(&Ag[0][arow][ak]);
        CPA16(da, Abase + ak, apred);
        unsigned db0 = (unsigned)__cvta_generic_to_shared(&Bg[0][brow][bcol]);
        unsigned db1 = (unsigned)__cvta_generic_to_shared(&Bg[0][16 + brow][bcol]);
        CPA16(db0, &B[(size_t)brow * DIM + bcol], 16);
        CPA16(db1, &B[(size_t)(16 + brow) * DIM + bcol], 16);
        asm volatile("cp.async.commit_group;");
    }

    for (int tt = 0; tt < T; tt++) {
        if (tt + 1 < T) {
            const int buf = (tt + 1) & 1, k0 = (tt + 1) * 32;
            unsigned da = (unsigned)__cvta_generic_to_shared(&Ag[buf][arow][ak]);
            CPA16(da, Abase + k0 + ak, apred);
            unsigned db0 = (unsigned)__cvta_generic_to_shared(&Bg[buf][brow][bcol]);
            unsigned db1 = (unsigned)__cvta_generic_to_shared(&Bg[buf][16 + brow][bcol]);
            CPA16(db0, &B[(size_t)(k0 + brow) * DIM + bcol], 16);
            CPA16(db1, &B[(size_t)(k0 + 16 + brow) * DIM + bcol], 16);
            asm volatile("cp.async.commit_group;");
            asm volatile("cp.async.wait_group 1;");
        } else {
            asm volatile("cp.async.wait_group 0;");
        }
        __syncthreads();

        const int buf = tt & 1;
        #pragma unroll
        for (int sub = 0; sub < 2; sub++) {
            const int kc = sub * 16;
            unsigned af[2][4];
            #pragma unroll
            for (int mt = 0; mt < 2; mt++) {
                const __half* p = &Ag[buf][wm + mt*16 + (lane & 15)][kc + ((lane >> 4) << 3)];
                unsigned addr = (unsigned)__cvta_generic_to_shared(p);
                asm volatile("ldmatrix.sync.aligned.m8n8.x4.shared.b16 {%0,%1,%2,%3}, [%4];"
                    : "=r"(af[mt][0]), "=r"(af[mt][1]), "=r"(af[mt][2]), "=r"(af[mt][3])
                    : "r"(addr));
            }
            unsigned bf[4][2];
            #pragma unroll
            for (int q = 0; q < 2; q++) {
                const __half* p = &Bg[buf][kc + (lane & 15)][wn + q*16 + ((lane >> 4) << 3)];
                unsigned addr = (unsigned)__cvta_generic_to_shared(p);
                asm volatile("ldmatrix.sync.aligned.m8n8.x4.trans.shared.b16 {%0,%1,%2,%3}, [%4];"
                    : "=r"(bf[q*2][0]), "=r"(bf[q*2][1]), "=r"(bf[q*2+1][0]), "=r"(bf[q*2+1][1])
                    : "r"(addr));
            }
            #pragma unroll
            for (int mt = 0; mt < 2; mt++)
                #pragma unroll
                for (int nt = 0; nt < 4; nt++) {
                    asm volatile(
                        "mma.sync.aligned.m16n8k16.row.col.f32.f16.f16.f32 "
                        "{%0,%1,%2,%3}, {%4,%5,%6,%7}, {%8,%9}, {%0,%1,%2,%3};"
                        : "+f"(acc[mt][nt][0]), "+f"(acc[mt][nt][1]),
                          "+f"(acc[mt][nt][2]), "+f"(acc[mt][nt][3])
                        : "r"(af[mt][0]), "r"(af[mt][1]), "r"(af[mt][2]), "r"(af[mt][3]),
                          "r"(bf[nt][0]), "r"(bf[nt][1]));
                }
        }
        __syncthreads();
    }

    // ---- second GEMM: z @ Ws ----
    const int T2 = K2 >> 5;
    for (int q = 0; q < T2; q++) {
        uint4 a0 = make_uint4(0,0,0,0);
        if (gm < N_NODES)
            a0 = *(const uint4*)&A2[(size_t)gm * K2 + q*32 + ak];
        uint4 b0 = *(const uint4*)&W2[(size_t)(q*32 + brow) * DIM + bcol];
        uint4 b1 = *(const uint4*)&W2[(size_t)(q*32 + 16 + brow) * DIM + bcol];
        __syncthreads();
        *(uint4*)&Ag[0][arow][ak] = a0;
        *(uint4*)&Bg[0][brow][bcol]      = b0;
        *(uint4*)&Bg[0][16 + brow][bcol] = b1;
        __syncthreads();

        #pragma unroll
        for (int sub = 0; sub < 2; sub++) {
            const int kc = sub * 16;
            unsigned af[2][4];
            #pragma unroll
            for (int mt = 0; mt < 2; mt++) {
                const __half* p = &Ag[0][wm + mt*16 + (lane & 15)][kc + ((lane >> 4) << 3)];
                unsigned addr = (unsigned)__cvta_generic_to_shared(p);
                asm volatile("ldmatrix.sync.aligned.m8n8.x4.shared.b16 {%0,%1,%2,%3}, [%4];"
                    : "=r"(af[mt][0]), "=r"(af[mt][1]), "=r"(af[mt][2]), "=r"(af[mt][3])
                    : "r"(addr));
            }
            unsigned bf[4][2];
            #pragma unroll
            for (int qq = 0; qq < 2; qq++) {
                const __half* p = &Bg[0][kc + (lane & 15)][wn + qq*16 + ((lane >> 4) << 3)];
                unsigned addr = (unsigned)__cvta_generic_to_shared(p);
                asm volatile("ldmatrix.sync.aligned.m8n8.x4.trans.shared.b16 {%0,%1,%2,%3}, [%4];"
                    : "=r"(bf[qq*2][0]), "=r"(bf[qq*2][1]), "=r"(bf[qq*2+1][0]), "=r"(bf[qq*2+1][1])
                    : "r"(addr));
            }
            #pragma unroll
            for (int mt = 0; mt < 2; mt++)
                #pragma unroll
                for (int nt = 0; nt < 4; nt++) {
                    asm volatile(
                        "mma.sync.aligned.m16n8k16.row.col.f32.f16.f16.f32 "
                        "{%0,%1,%2,%3}, {%4,%5,%6,%7}, {%8,%9}, {%0,%1,%2,%3};"
                        : "+f"(acc[mt][nt][0]), "+f"(acc[mt][nt][1]),
                          "+f"(acc[mt][nt][2]), "+f"(acc[mt][nt][3])
                        : "r"(af[mt][0]), "r"(af[mt][1]), "r"(af[mt][2]), "r"(af[mt][3]),
                          "r"(bf[nt][0]), "r"(bf[nt][1]));
                }
        }
        __syncthreads();
    }

    // ---- epilogue 1: zi-tile = silu(acc + bs) -> R (fp32) + As (fp16) ----
    #pragma unroll
    for (int mt = 0; mt < 2; mt++) {
        #pragma unroll
        for (int nt = 0; nt < 4; nt++) {
            int col = wn + nt*8 + 2*t4;
            float b0 = bs[col], b1 = bs[col + 1];
            #pragma unroll
            for (int h = 0; h < 2; h++) {
                int rl = wm + mt*16 + g4 + h*8;
                float ox = silu_f(acc[mt][nt][h*2 + 0] + b0);
                float oy = silu_f(acc[mt][nt][h*2 + 1] + b1);
                R[rl][col] = ox; R[rl][col + 1] = oy;
                *(__half2*)&As[rl][col] = __floats2half2_rn(ox, oy);
            }
        }
    }
    __syncthreads();

    // ---- phase 2: 3x onsite blocks ----
    const int rw = t >> 1, cw = (t & 1) * 64;
    for (int j = 0; j < 3; j++) {
        const __half* Wa = WaBase + j * DIM * DIM;
        const __half* Wb = WbBase + j * DIM * DIM;
        const float*  ba = baBase + j * DIM;
        const float*  bb = bbBase + j * DIM;

        #pragma unroll
        for (int i = 0; i < 8; i++)
            *(uint4*)&Ws[rw][cw + i*8] = *(const uint4*)&Wa[rw * DIM + cw + i*8];
        __syncthreads();

        #pragma unroll
        for (int mt = 0; mt < 2; mt++)
            #pragma unroll
            for (int nt = 0; nt < 4; nt++)
                #pragma unroll
                for (int i = 0; i < 4; i++) acc[mt][nt][i] = 0.0f;

        #pragma unroll
        for (int kc = 0; kc < 128; kc += 16) {
            unsigned af[2][4];
            #pragma unroll
            for (int mt = 0; mt < 2; mt++) {
                const __half* p = &As[wm + mt*16 + (lane & 15)][kc + ((lane >> 4) << 3)];
                unsigned addr = (unsigned)__cvta_generic_to_shared(p);
                asm volatile("ldmatrix.sync.aligned.m8n8.x4.shared.b16 {%0,%1,%2,%3}, [%4];"
                    : "=r"(af[mt][0]), "=r"(af[mt][1]), "=r"(af[mt][2]), "=r"(af[mt][3])
                    : "r"(addr));
            }
            unsigned bf[4][2];
            #pragma unroll
            for (int q = 0; q < 2; q++) {
                const __half* p = &Ws[kc + (lane & 15)][wn + q*16 + ((lane >> 4) << 3)];
                unsigned addr = (unsigned)__cvta_generic_to_shared(p);
                asm volatile("ldmatrix.sync.aligned.m8n8.x4.trans.shared.b16 {%0,%1,%2,%3}, [%4];"
                    : "=r"(bf[q*2][0]), "=r"(bf[q*2][1]), "=r"(bf[q*2+1][0]), "=r"(bf[q*2+1][1])
                    : "r"(addr));
            }
            #pragma unroll
            for (int mt = 0; mt < 2; mt++)
                #pragma unroll
                for (int nt = 0; nt < 4; nt++) {
                    asm volatile(
                        "mma.sync.aligned.m16n8k16.row.col.f32.f16.f16.f32 "
                        "{%0,%1,%2,%3}, {%4,%5,%6,%7}, {%8,%9}, {%0,%1,%2,%3};"
                        : "+f"(acc[mt][nt][0]), "+f"(acc[mt][nt][1]),
                          "+f"(acc[mt][nt][2]), "+f"(acc[mt][nt][3])
                        : "r"(af[mt][0]), "r"(af[mt][1]), "r"(af[mt][2]), "r"(af[mt][3]),
                          "r"(bf[nt][0]), "r"(bf[nt][1]));
                }
        }
        __syncthreads();

        #pragma unroll
        for (int mt = 0; mt < 2; mt++) {
            #pragma unroll
            for (int nt = 0; nt < 4; nt++) {
                int col = wn + nt*8 + 2*t4;
                float b0 = ba[col], b1 = ba[col + 1];
                int r0 = wm + mt*16 + g4;
                *(__half2*)&As[r0][col] =
                    __floats2half2_rn(silu_f(acc[mt][nt][0] + b0), silu_f(acc[mt][nt][1] + b1));
                *(__half2*)&As[r0 + 8][col] =
                    __floats2half2_rn(silu_f(acc[mt][nt][2] + b0), silu_f(acc[mt][nt][3] + b1));
            }
        }
        #pragma unroll
        for (int i = 0; i < 8; i++)
            *(uint4*)&Ws[rw][cw + i*8] = *(const uint4*)&Wb[rw * DIM + cw + i*8];
        __syncthreads();

        #pragma unroll
        for (int mt = 0; mt < 2; mt++)
            #pragma unroll
            for (int nt = 0; nt < 4; nt++)
                #pragma unroll
                for (int i = 0; i < 4; i++) acc[mt][nt][i] = 0.0f;

        #pragma unroll
        for (int kc = 0; kc < 128; kc += 16) {
            unsigned af[2][4];
            #pragma unroll
            for (int mt = 0; mt < 2; mt++) {
                const __half* p = &As[wm + mt*16 + (lane & 15)][kc + ((lane >> 4) << 3)];
                unsigned addr = (unsigned)__cvta_generic_to_shared(p);
                asm volatile("ldmatrix.sync.aligned.m8n8.x4.shared.b16 {%0,%1,%2,%3}, [%4];"
                    : "=r"(af[mt][0]), "=r"(af[mt][1]), "=r"(af[mt][2]), "=r"(af[mt][3])
                    : "r"(addr));
            }
            unsigned bf[4][2];
            #pragma unroll
            for (int q = 0; q < 2; q++) {
                const __half* p = &Ws[kc + (lane & 15)][wn + q*16 + ((lane >> 4) << 3)];
                unsigned addr = (unsigned)__cvta_generic_to_shared(p);
                asm volatile("ldmatrix.sync.aligned.m8n8.x4.trans.shared.b16 {%0,%1,%2,%3}, [%4];"
                    : "=r"(bf[q*2][0]), "=r"(bf[q*2][1]), "=r"(bf[q*2+1][0]), "=r"(bf[q*2+1][1])
                    : "r"(addr));
            }
            #pragma unroll
            for (int mt = 0; mt < 2; mt++)
                #pragma unroll
                for (int nt = 0; nt < 4; nt++) {
                    asm volatile(
                        "mma.sync.aligned.m16n8k16.row.col.f32.f16.f16.f32 "
                        "{%0,%1,%2,%3}, {%4,%5,%6,%7}, {%8,%9}, {%0,%1,%2,%3};"
                        : "+f"(acc[mt][nt][0]), "+f"(acc[mt][nt][1]),
                          "+f"(acc[mt][nt][2]), "+f"(acc[mt][nt][3])
                        : "r"(af[mt][0]), "r"(af[mt][1]), "r"(af[mt][2]), "r"(af[mt][3]),
                          "r"(bf[nt][0]), "r"(bf[nt][1]));
                }
        }
        __syncthreads();

        #pragma unroll
        for (int mt = 0; mt < 2; mt++) {
            #pragma unroll
            for (int nt = 0; nt < 4; nt++) {
                int col = wn + nt*8 + 2*t4;
                float b0 = bb[col], b1 = bb[col + 1];
                #pragma unroll
                for (int h = 0; h < 2; h++) {
                    int rl = wm + mt*16 + g4 + h*8;
                    float2 o;
                    o.x = acc[mt][nt][h*2 + 0] + b0 + R[rl][col];
                    o.y = acc[mt][nt][h*2 + 1] + b1 + R[rl][col + 1];
                    if (j < 2) {
                        R[rl][col] = o.x; R[rl][col + 1] = o.y;
                        *(__half2*)&As[rl][col] = __floats2half2_rn(o.x, o.y);
                    } else {
                        int row = m0 + rl;
                        if (row < N_NODES) {
                            if (LAYER == 0) {
                                *(__half2*)&zih_out[(size_t)row * DIM + col] =
                                    __floats2half2_rn(o.x, o.y);
                                *(float2*)&out[(size_t)N_NODES * DIM + (size_t)row * 2 * DIM + col] = o;
                            } else {
                                *(float2*)&out[(size_t)row * DIM + col] = o;
                                *(float2*)&out[(size_t)N_NODES * DIM + (size_t)row * 2 * DIM + DIM + col] = o;
                            }
                        }
                    }
                }
            }
        }
        __syncthreads();
    }
}

// ---------------- host driver ----------------
extern "C" void kernel_launch(void* const* d_in, const int* in_sizes, int n_in,
                              void* d_out, int out_size)
{
    const int*   species = (const int*)  d_in[0];
    const int*   esrc    = (const int*)  d_in[1];
    const int*   edst    = (const int*)  d_in[2];
    const float* dist    = (const float*)d_in[3];
    const float* swp     = (const float*)d_in[4];
    const float* Z       = (const float*)d_in[5];
    const float* Ws0     = (const float*)d_in[6];
    const float* bs0     = (const float*)d_in[7];
    const float* V0      = (const float*)d_in[8];
    const float* Ws1     = (const float*)d_in[9];
    const float* bs1     = (const float*)d_in[10];
    const float* V1      = (const float*)d_in[11];
    const float* Won_a   = (const float*)d_in[12];
    const float* bon_a   = (const float*)d_in[13];
    const float* Won_b   = (const float*)d_in[14];
    const float* bon_b   = (const float*)d_in[15];
    float* out = (float*)d_out;

    __half *Ah, *Vh0, *Vh1, *z16h, *zih, *Ws0h, *Ws1h, *Wah, *Wbh;
    cudaGetSymbolAddress((void**)&Ah,    g_A);
    cudaGetSymbolAddress((void**)&Vh0,   g_Vh0);
    cudaGetSymbolAddress((void**)&Vh1,   g_Vh1);
    cudaGetSymbolAddress((void**)&z16h,  g_z16h);
    cudaGetSymbolAddress((void**)&zih,   g_zih);
    cudaGetSymbolAddress((void**)&Ws0h,  g_Ws0h);
    cudaGetSymbolAddress((void**)&Ws1h,  g_Ws1h);
    cudaGetSymbolAddress((void**)&Wah,   g_Wah);
    cudaGetSymbolAddress((void**)&Wbh,   g_Wbh);

    const int MB64 = (N_NODES + 63) / 64;       // 313
    const int EB = (N_EDGES + 255) / 256;
    const int NBK = (N_NODES + 7) / 8;
    const int PREP_N = N_NODES * 32;            // 640000 >= N_EDGES

    const int NODE_SMEM  = 17408 + 34816 + 64 * DIM * 4;   // 84992
    const int EDGE1_SMEM = 12288 + 69632;                  // 81920
    static int attr_done = 0;
    if (!attr_done) {
        cudaFuncSetAttribute(k_nodeP<0>, cudaFuncAttributeMaxDynamicSharedMemorySize, NODE_SMEM);
        cudaFuncSetAttribute(k_nodeP<1>, cudaFuncAttributeMaxDynamicSharedMemorySize, NODE_SMEM);
        cudaFuncSetAttribute(k_edgeT1,   cudaFuncAttributeMaxDynamicSharedMemorySize, EDGE1_SMEM);
        attr_done = 1;
    }

    // ---- preprocessing ----
    k_prep<<<(PREP_N + 255) / 256, 256>>>(species, Z, V0, V1, Ws0, Ws1, Won_a, Won_b, esrc);
    k_scan1<<<SCAN_BLKS, 256>>>();
    k_scan2<<<1, 128>>>();
    k_scan3<<<SCAN_BLKS, 256>>>();
    k_fillS<<<EB, 256>>>(esrc, edst, dist, swp);

    // ---- layer 0 ----
    k_edgeT0<<<NBK, 256>>>();
    k_nodeP<0><<<MB64, 256, NODE_SMEM>>>(Ah, Vh0, z16h, Ws0h, bs0,
        Wah + 0*3*DIM*DIM, bon_a + 0*3*DIM, Wbh + 0*3*DIM*DIM, bon_b + 0*3*DIM,
        zih, out, KT0, 32);

    // ---- layer 1 ----
    k_edgeT1<<<NBK, 256, EDGE1_SMEM>>>();
    k_nodeP<1><<<MB64, 256, NODE_SMEM>>>(Ah, Vh1, zih, Ws1h, bs1,
        Wah + 1*3*DIM*DIM, bon_a + 1*3*DIM, Wbh + 1*3*DIM*DIM, bon_b + 1*3*DIM,
        zih, out, KT1, DIM);
}